// round 6
// baseline (speedup 1.0000x reference)
#include <cuda_runtime.h>
#include <math.h>

#define NB 8
#define LQ 2048
#define DD 512
#define DECAYF 0.2f
#define QP 516      // Q tile smem row stride (pad ≡ 4 mod 32 -> conflict-free A-frag LDS)
#define KP 516      // K/V tile smem row stride
#define PP 36       // P tile smem row stride

// Scratch (device globals: allocation-free per harness rules)
__device__ float g_Xs[NB * LQ * DD];
__device__ float g_Xt[NB * LQ * DD];
__device__ float g_cat[NB * LQ * 2 * DD];

// ---------------------------------------------------------------------------
// tf32 mma.sync helper: D += A(16x8) * B(8x8), accumulate in place
// ---------------------------------------------------------------------------
__device__ __forceinline__ void mma_tf32(float* c,
                                         unsigned a0, unsigned a1, unsigned a2, unsigned a3,
                                         unsigned b0, unsigned b1) {
    asm volatile(
        "mma.sync.aligned.m16n8k8.row.col.f32.tf32.tf32.f32 "
        "{%0,%1,%2,%3}, {%4,%5,%6,%7}, {%8,%9}, {%0,%1,%2,%3};\n"
        : "+f"(c[0]), "+f"(c[1]), "+f"(c[2]), "+f"(c[3])
        : "r"(a0), "r"(a1), "r"(a2), "r"(a3), "r"(b0), "r"(b1));
}

// Dekker split: x = hi(tf32-truncated) + lo. hi·hi + hi·lo + lo·hi ~ fp32 acc.
__device__ __forceinline__ void split2(float x, unsigned& hi, unsigned& lo) {
    unsigned xb = __float_as_uint(x);
    hi = xb & 0xffffe000u;
    lo = __float_as_uint(x - __uint_as_float(hi));
}

// ---------------------------------------------------------------------------
// Block-wide sum reduction (256 threads) for prep
// ---------------------------------------------------------------------------
__device__ __forceinline__ float blockReduceSum(float v, float* red) {
    #pragma unroll
    for (int o = 16; o > 0; o >>= 1) v += __shfl_xor_sync(0xffffffffu, v, o);
    int tid = threadIdx.x;
    if ((tid & 31) == 0) red[tid >> 5] = v;
    __syncthreads();
    if (tid < 32) {
        float x = (tid < 8) ? red[tid] : 0.f;
        #pragma unroll
        for (int o = 4; o > 0; o >>= 1) x += __shfl_xor_sync(0xffffffffu, x, o);
        if (tid == 0) red[0] = x;
    }
    __syncthreads();
    float r = red[0];
    __syncthreads();
    return r;
}

__device__ __forceinline__ void routing2(const float u0[2], const float u1[2],
                                         float vout[2], float* red) {
    float b0 = 0.f, b1 = 0.f;
    #pragma unroll
    for (int it = 0; it < 3; it++) {
        float mx = fmaxf(b0, b1);
        float e0 = __expf(b0 - mx), e1 = __expf(b1 - mx);
        float inv = 1.f / (e0 + e1);
        float c0 = e0 * inv, c1 = e1 * inv;
        float s0 = c0 * u0[0] + c1 * u1[0];
        float s1 = c0 * u0[1] + c1 * u1[1];
        float n2 = blockReduceSum(s0 * s0 + s1 * s1, red);
        float nrm = sqrtf(n2);
        float scl = n2 / ((1.f + n2) * (nrm + 1e-9f));
        vout[0] = scl * s0;
        vout[1] = scl * s1;
        if (it < 2) {
            b0 += blockReduceSum(u0[0] * vout[0] + u0[1] * vout[1], red);
            b1 += blockReduceSum(u1[0] * vout[0] + u1[1] * vout[1], red);
        }
    }
}

// ---------------------------------------------------------------------------
// Kernel 1: causal depthwise convs + capsule routing
// ---------------------------------------------------------------------------
__global__ void prep_kernel(const float* __restrict__ x,
                            const float* __restrict__ w3,
                            const float* __restrict__ w5) {
    __shared__ float red[8];
    int row = blockIdx.x;
    int n = row >> 11;
    int l = row & 2047;
    int tid = threadIdx.x;

    float xv[2], t3v[2], t5v[2];
    #pragma unroll
    for (int i = 0; i < 2; i++) {
        int c = tid + i * 256;
        const float* xb = x + (size_t)n * LQ * DD + c;
        float a3 = 0.f, a5 = 0.f, xx = 0.f;
        #pragma unroll
        for (int j = 0; j < 5; j++) {
            int ll = l - 4 + j;
            xx = (ll >= 0) ? xb[(size_t)ll * DD] : 0.f;
            a5 += w5[c * 5 + j] * xx;
            if (j >= 2) a3 += w3[c * 3 + (j - 2)] * xx;
        }
        xv[i] = xx; t3v[i] = a3; t5v[i] = a5;
    }

    float u0[2], u1[2], v[2];
    u0[0] = xv[0] - t3v[0]; u0[1] = xv[1] - t3v[1];
    u1[0] = xv[0] - t5v[0]; u1[1] = xv[1] - t5v[1];
    routing2(u0, u1, v, red);
    g_Xs[(size_t)row * DD + tid]       = v[0];
    g_Xs[(size_t)row * DD + tid + 256] = v[1];

    u0[0] = t3v[0]; u0[1] = t3v[1];
    u1[0] = t5v[0]; u1[1] = t5v[1];
    routing2(u0, u1, v, red);
    g_Xt[(size_t)row * DD + tid]       = v[0];
    g_Xt[(size_t)row * DD + tid + 256] = v[1];
}

// ---------------------------------------------------------------------------
// Kernel 2: flash attention, tf32 mma.sync 3-pass, 32x32 tiles
// grid = (L/32, N, 2), 256 threads
// ---------------------------------------------------------------------------
__global__ void __launch_bounds__(256, 1) attn_kernel() {
    extern __shared__ float sm[];
    float* Qs     = sm;                  // 32 x QP
    float* Ks     = Qs + 32 * QP;        // 32 x KP (keys == values)
    float* Ps     = Ks + 32 * KP;        // 32 x PP
    float* redm   = Ps + 32 * PP;        // 4 x 32
    float* redl   = redm + 128;          // 4 x 32
    float* m_s    = redl + 128;          // 32
    float* l_s    = m_s + 32;            // 32
    float* corr_s = l_s + 32;            // 32

    int zb = blockIdx.z;
    const float* X = zb ? g_Xt : g_Xs;
    int n = blockIdx.y;
    int qb = blockIdx.x;
    int tid = threadIdx.x;
    int w = tid >> 5, lane = tid & 31;
    int g4 = lane >> 2, tig = lane & 3;
    const float* Xn = X + (size_t)n * LQ * DD;
    int q0 = qb * 32;

    // load Q tile
    for (int i = tid; i < 32 * 128; i += 256) {
        int r = i >> 7, c4 = i & 127;
        *(float4*)&Qs[r * QP + c4 * 4] = ((const float4*)(Xn + (size_t)(q0 + r) * DD))[c4];
    }
    if (tid < 32) { m_s[tid] = -3.0e30f; l_s[tid] = 0.f; }

    // partitions: scores: warp = (rg rowgroup of 16) x (cg colgroup of 8)
    //             PV:     warp = (rg rowgroup of 16) x (cg2 colgroup of 128)
    int rg = w & 1, cg = w >> 1;

    float acc[16][4];
    #pragma unroll
    for (int i = 0; i < 16; i++) { acc[i][0] = acc[i][1] = acc[i][2] = acc[i][3] = 0.f; }

    int ar0 = (rg * 16 + g4) * QP;
    int ar1 = (rg * 16 + g4 + 8) * QP;
    int br  = (cg * 8 + g4) * KP;
    int par0 = (rg * 16 + g4) * PP;
    int par1 = (rg * 16 + g4 + 8) * PP;

    for (int kb = 0; kb <= qb; kb++) {
        __syncthreads();                        // S1: protect Ks/Ps/redl
        for (int i = tid; i < 32 * 128; i += 256) {
            int r = i >> 7, c4 = i & 127;
            *(float4*)&Ks[r * KP + c4 * 4] = ((const float4*)(Xn + (size_t)(kb * 32 + r) * DD))[c4];
        }
        __syncthreads();                        // S2: Ks ready

        // --- scores: S = Q K^T, 3-pass tf32 ---
        float sc[4] = {0.f, 0.f, 0.f, 0.f};
        #pragma unroll 8
        for (int ks = 0; ks < 64; ks++) {
            int k0 = ks * 8;
            unsigned h0, l0, h1, l1, h2, l2, h3, l3, hb0, lb0, hb1, lb1;
            split2(Qs[ar0 + k0 + tig],     h0, l0);
            split2(Qs[ar1 + k0 + tig],     h1, l1);
            split2(Qs[ar0 + k0 + tig + 4], h2, l2);
            split2(Qs[ar1 + k0 + tig + 4], h3, l3);
            split2(Ks[br + k0 + tig],      hb0, lb0);
            split2(Ks[br + k0 + tig + 4],  hb1, lb1);
            mma_tf32(sc, h0, h1, h2, h3, hb0, hb1);
            mma_tf32(sc, h0, h1, h2, h3, lb0, lb1);
            mma_tf32(sc, l0, l1, l2, l3, hb0, hb1);
        }
        // bias + causal mask
        int r0 = q0 + rg * 16 + g4, r1 = r0 + 8;
        int c0 = kb * 32 + cg * 8 + 2 * tig, c1 = c0 + 1;
        sc[0] = (r0 >= c0) ? sc[0] - DECAYF * (float)(r0 - c0) : -3.0e30f;
        sc[1] = (r0 >= c1) ? sc[1] - DECAYF * (float)(r0 - c1) : -3.0e30f;
        sc[2] = (r1 >= c0) ? sc[2] - DECAYF * (float)(r1 - c0) : -3.0e30f;
        sc[3] = (r1 >= c1) ? sc[3] - DECAYF * (float)(r1 - c1) : -3.0e30f;

        // warp-level row max over this warp's 8 cols
        float m0 = fmaxf(sc[0], sc[1]);
        float m1 = fmaxf(sc[2], sc[3]);
        m0 = fmaxf(m0, __shfl_xor_sync(0xffffffffu, m0, 1));
        m0 = fmaxf(m0, __shfl_xor_sync(0xffffffffu, m0, 2));
        m1 = fmaxf(m1, __shfl_xor_sync(0xffffffffu, m1, 1));
        m1 = fmaxf(m1, __shfl_xor_sync(0xffffffffu, m1, 2));
        if (tig == 0) {
            redm[cg * 32 + rg * 16 + g4]     = m0;
            redm[cg * 32 + rg * 16 + g4 + 8] = m1;
        }
        __syncthreads();                        // S3: redm ready
        if (w == 0) {
            int r = lane;
            float tm = fmaxf(fmaxf(redm[r], redm[32 + r]), fmaxf(redm[64 + r], redm[96 + r]));
            float mo = m_s[r];
            float mn = fmaxf(mo, tm);
            m_s[r] = mn;
            corr_s[r] = __expf(mo - mn);
        }
        __syncthreads();                        // S4: m_s/corr_s ready

        // P = exp(S - m), write to Ps + partial sums
        {
            float mn0 = m_s[rg * 16 + g4];
            float mn1 = m_s[rg * 16 + g4 + 8];
            float p0 = __expf(sc[0] - mn0);
            float p1 = __expf(sc[1] - mn0);
            float p2 = __expf(sc[2] - mn1);
            float p3 = __expf(sc[3] - mn1);
            *(float2*)&Ps[par0 + cg * 8 + 2 * tig] = make_float2(p0, p1);
            *(float2*)&Ps[par1 + cg * 8 + 2 * tig] = make_float2(p2, p3);
            float s0 = p0 + p1, s1 = p2 + p3;
            s0 += __shfl_xor_sync(0xffffffffu, s0, 1);
            s0 += __shfl_xor_sync(0xffffffffu, s0, 2);
            s1 += __shfl_xor_sync(0xffffffffu, s1, 1);
            s1 += __shfl_xor_sync(0xffffffffu, s1, 2);
            if (tig == 0) {
                redl[cg * 32 + rg * 16 + g4]     = s0;
                redl[cg * 32 + rg * 16 + g4 + 8] = s1;
            }
        }
        __syncthreads();                        // S5: Ps + redl ready
        if (w == 0) {
            int r = lane;
            l_s[r] = l_s[r] * corr_s[r] + redl[r] + redl[32 + r] + redl[64 + r] + redl[96 + r];
        }

        // --- PV: O += P V, 3-pass tf32 ---
        float cr0 = corr_s[rg * 16 + g4];
        float cr1 = corr_s[rg * 16 + g4 + 8];
        #pragma unroll
        for (int nf = 0; nf < 16; nf++) {
            acc[nf][0] *= cr0; acc[nf][1] *= cr0;
            acc[nf][2] *= cr1; acc[nf][3] *= cr1;
        }
        #pragma unroll
        for (int ks = 0; ks < 4; ks++) {
            int k0 = ks * 8;
            unsigned h0, l0, h1, l1, h2, l2, h3, l3;
            split2(Ps[par0 + k0 + tig],     h0, l0);
            split2(Ps[par1 + k0 + tig],     h1, l1);
            split2(Ps[par0 + k0 + tig + 4], h2, l2);
            split2(Ps[par1 + k0 + tig + 4], h3, l3);
            int vb0 = (k0 + tig) * KP;
            int vb1 = (k0 + tig + 4) * KP;
            #pragma unroll
            for (int nf = 0; nf < 16; nf++) {
                int n0 = cg * 128 + nf * 8 + g4;
                unsigned hv0, lv0, hv1, lv1;
                split2(Ks[vb0 + n0], hv0, lv0);
                split2(Ks[vb1 + n0], hv1, lv1);
                mma_tf32(acc[nf], h0, h1, h2, h3, hv0, hv1);
                mma_tf32(acc[nf], h0, h1, h2, h3, lv0, lv1);
                mma_tf32(acc[nf], l0, l1, l2, l3, hv0, hv1);
            }
        }
    }
    __syncthreads();

    float li0 = 1.f / l_s[rg * 16 + g4];
    float li1 = 1.f / l_s[rg * 16 + g4 + 8];
    int orow0 = n * LQ + q0 + rg * 16 + g4;
    int orow1 = orow0 + 8;
    #pragma unroll
    for (int nf = 0; nf < 16; nf++) {
        int col = zb * DD + cg * 128 + nf * 8 + 2 * tig;
        *(float2*)&g_cat[(size_t)orow0 * (2 * DD) + col] =
            make_float2(acc[nf][0] * li0, acc[nf][1] * li0);
        *(float2*)&g_cat[(size_t)orow1 * (2 * DD) + col] =
            make_float2(acc[nf][2] * li1, acc[nf][3] * li1);
    }
}

// ---------------------------------------------------------------------------
// Kernel 3: out[16384,512] = g_cat[16384,1024] @ W[512,1024]^T + bias
// tf32 mma.sync 3-pass, 64x64 tiles
// ---------------------------------------------------------------------------
__global__ void __launch_bounds__(256) fusion_kernel(const float* __restrict__ W,
                                                     const float* __restrict__ bias,
                                                     float* __restrict__ out) {
    __shared__ float As[64 * 36];
    __shared__ float Bs[64 * 36];
    int bm = blockIdx.x * 64;
    int bn = blockIdx.y * 64;
    int tid = threadIdx.x;
    int w = tid >> 5, lane = tid & 31;
    int g4 = lane >> 2, tig = lane & 3;
    int rg = w & 3, cg = w >> 2;

    float acc[4][4];
    #pragma unroll
    for (int i = 0; i < 4; i++) { acc[i][0] = acc[i][1] = acc[i][2] = acc[i][3] = 0.f; }

    int ar0 = (rg * 16 + g4) * 36;
    int ar1 = (rg * 16 + g4 + 8) * 36;

    for (int kc = 0; kc < 32; kc++) {
        __syncthreads();
        #pragma unroll
        for (int i = 0; i < 2; i++) {
            int idx = tid + i * 256;
            int r = idx >> 3, c = idx & 7;
            *(float4*)&As[r * 36 + c * 4] =
                *(const float4*)&g_cat[(size_t)(bm + r) * 1024 + kc * 32 + c * 4];
            *(float4*)&Bs[r * 36 + c * 4] =
                *(const float4*)&W[(size_t)(bn + r) * 1024 + kc * 32 + c * 4];
        }
        __syncthreads();
        #pragma unroll
        for (int ks = 0; ks < 4; ks++) {
            int k0 = ks * 8;
            unsigned h0, l0, h1, l1, h2, l2, h3, l3;
            split2(As[ar0 + k0 + tig],     h0, l0);
            split2(As[ar1 + k0 + tig],     h1, l1);
            split2(As[ar0 + k0 + tig + 4], h2, l2);
            split2(As[ar1 + k0 + tig + 4], h3, l3);
            #pragma unroll
            for (int nf = 0; nf < 4; nf++) {
                int brow = (cg * 32 + nf * 8 + g4) * 36;
                unsigned hb0, lb0, hb1, lb1;
                split2(Bs[brow + k0 + tig],     hb0, lb0);
                split2(Bs[brow + k0 + tig + 4], hb1, lb1);
                mma_tf32(acc[nf], h0, h1, h2, h3, hb0, hb1);
                mma_tf32(acc[nf], h0, h1, h2, h3, lb0, lb1);
                mma_tf32(acc[nf], l0, l1, l2, l3, hb0, hb1);
            }
        }
    }

    int orow0 = bm + rg * 16 + g4, orow1 = orow0 + 8;
    #pragma unroll
    for (int nf = 0; nf < 4; nf++) {
        int col = bn + cg * 32 + nf * 8 + 2 * tig;
        float b0v = bias[col], b1v = bias[col + 1];
        *(float2*)&out[(size_t)orow0 * 512 + col] = make_float2(acc[nf][0] + b0v, acc[nf][1] + b1v);
        *(float2*)&out[(size_t)orow1 * 512 + col] = make_float2(acc[nf][2] + b0v, acc[nf][3] + b1v);
    }
}

// ---------------------------------------------------------------------------
extern "C" void kernel_launch(void* const* d_in, const int* in_sizes, int n_in,
                              void* d_out, int out_size) {
    const float* x  = (const float*)d_in[0];
    const float* w3 = (const float*)d_in[1];
    const float* w5 = (const float*)d_in[2];
    const float* fw = (const float*)d_in[3];
    const float* fb = (const float*)d_in[4];
    float* out = (float*)d_out;

    prep_kernel<<<NB * LQ, 256>>>(x, w3, w5);

    size_t smem = (size_t)(32 * QP + 32 * KP + 32 * PP + 128 + 128 + 96) * sizeof(float);
    cudaFuncSetAttribute(attn_kernel,
                         cudaFuncAttributeMaxDynamicSharedMemorySize, (int)smem);
    dim3 ga(LQ / 32, NB, 2);
    attn_kernel<<<ga, 256, smem>>>();

    dim3 gf((NB * LQ) / 64, DD / 64);
    fusion_kernel<<<gf, 256>>>(fw, fb, out);
}

// round 7
// speedup vs baseline: 1.6923x; 1.6923x over previous
#include <cuda_runtime.h>
#include <cuda_bf16.h>
#include <math.h>

#define NB 8
#define LQ 2048
#define DD 512
#define DECAYF 0.2f
#define KQS 520      // K/Q smem tile stride in bf16 elems (1040B: 16B-aligned, banks 4r mod 32)
#define PS2 40       // P tile stride in bf16 elems (80B)

// smem byte offsets for attn kernel
#define OFF_QHI 0
#define OFF_QLO 33280
#define OFF_KHI 66560
#define OFF_KLO 99840
#define OFF_PHI 133120
#define OFF_PLO 135680
#define OFF_RED 138240
#define SMEM_ATTN (OFF_RED + 1408)

// Scratch (device globals: allocation-free per harness rules)
__device__ __nv_bfloat16 g_Xs_hi[NB * LQ * DD];
__device__ __nv_bfloat16 g_Xs_lo[NB * LQ * DD];
__device__ __nv_bfloat16 g_Xt_hi[NB * LQ * DD];
__device__ __nv_bfloat16 g_Xt_lo[NB * LQ * DD];
__device__ __nv_bfloat16 g_cat_hi[NB * LQ * 2 * DD];
__device__ __nv_bfloat16 g_cat_lo[NB * LQ * 2 * DD];
__device__ __nv_bfloat16 g_W_hi[DD * 2 * DD];
__device__ __nv_bfloat16 g_W_lo[DD * 2 * DD];

// ---------------------------------------------------------------------------
// mma / ldmatrix helpers
// ---------------------------------------------------------------------------
__device__ __forceinline__ void ldmx4(unsigned* r, unsigned a) {
    asm volatile("ldmatrix.sync.aligned.m8n8.x4.shared.b16 {%0,%1,%2,%3}, [%4];"
        : "=r"(r[0]), "=r"(r[1]), "=r"(r[2]), "=r"(r[3]) : "r"(a));
}
__device__ __forceinline__ void ldmx2(unsigned* r, unsigned a) {
    asm volatile("ldmatrix.sync.aligned.m8n8.x2.shared.b16 {%0,%1}, [%2];"
        : "=r"(r[0]), "=r"(r[1]) : "r"(a));
}
__device__ __forceinline__ void ldmx2t(unsigned* r, unsigned a) {
    asm volatile("ldmatrix.sync.aligned.m8n8.x2.trans.shared.b16 {%0,%1}, [%2];"
        : "=r"(r[0]), "=r"(r[1]) : "r"(a));
}
__device__ __forceinline__ void mma_bf16(float* c, const unsigned* a, const unsigned* b) {
    asm volatile("mma.sync.aligned.m16n8k16.row.col.f32.bf16.bf16.f32 "
        "{%0,%1,%2,%3}, {%4,%5,%6,%7}, {%8,%9}, {%0,%1,%2,%3};"
        : "+f"(c[0]), "+f"(c[1]), "+f"(c[2]), "+f"(c[3])
        : "r"(a[0]), "r"(a[1]), "r"(a[2]), "r"(a[3]), "r"(b[0]), "r"(b[1]));
}
__device__ __forceinline__ void bsplit(float x, __nv_bfloat16& h, __nv_bfloat16& l) {
    h = __float2bfloat16(x);
    l = __float2bfloat16(x - __bfloat162float(h));
}
__device__ __forceinline__ unsigned pack2(__nv_bfloat16 a, __nv_bfloat16 b) {
    return ((unsigned)__bfloat16_as_ushort(b) << 16) | (unsigned)__bfloat16_as_ushort(a);
}

// ---------------------------------------------------------------------------
// prep: convs + routing, writes bf16 hi/lo planes
// ---------------------------------------------------------------------------
__device__ __forceinline__ float blockReduceSum(float v, float* red) {
    #pragma unroll
    for (int o = 16; o > 0; o >>= 1) v += __shfl_xor_sync(0xffffffffu, v, o);
    int tid = threadIdx.x;
    if ((tid & 31) == 0) red[tid >> 5] = v;
    __syncthreads();
    if (tid < 32) {
        float x = (tid < 8) ? red[tid] : 0.f;
        #pragma unroll
        for (int o = 4; o > 0; o >>= 1) x += __shfl_xor_sync(0xffffffffu, x, o);
        if (tid == 0) red[0] = x;
    }
    __syncthreads();
    float r = red[0];
    __syncthreads();
    return r;
}

__device__ __forceinline__ void routing2(const float u0[2], const float u1[2],
                                         float vout[2], float* red) {
    float b0 = 0.f, b1 = 0.f;
    #pragma unroll
    for (int it = 0; it < 3; it++) {
        float mx = fmaxf(b0, b1);
        float e0 = __expf(b0 - mx), e1 = __expf(b1 - mx);
        float inv = 1.f / (e0 + e1);
        float c0 = e0 * inv, c1 = e1 * inv;
        float s0 = c0 * u0[0] + c1 * u1[0];
        float s1 = c0 * u0[1] + c1 * u1[1];
        float n2 = blockReduceSum(s0 * s0 + s1 * s1, red);
        float nrm = sqrtf(n2);
        float scl = n2 / ((1.f + n2) * (nrm + 1e-9f));
        vout[0] = scl * s0;
        vout[1] = scl * s1;
        if (it < 2) {
            b0 += blockReduceSum(u0[0] * vout[0] + u0[1] * vout[1], red);
            b1 += blockReduceSum(u1[0] * vout[0] + u1[1] * vout[1], red);
        }
    }
}

__global__ void prep_kernel(const float* __restrict__ x,
                            const float* __restrict__ w3,
                            const float* __restrict__ w5) {
    __shared__ float red[8];
    int row = blockIdx.x;
    int n = row >> 11;
    int l = row & 2047;
    int tid = threadIdx.x;

    float xv[2], t3v[2], t5v[2];
    #pragma unroll
    for (int i = 0; i < 2; i++) {
        int c = tid + i * 256;
        const float* xb = x + (size_t)n * LQ * DD + c;
        float a3 = 0.f, a5 = 0.f, xx = 0.f;
        #pragma unroll
        for (int j = 0; j < 5; j++) {
            int ll = l - 4 + j;
            xx = (ll >= 0) ? xb[(size_t)ll * DD] : 0.f;
            a5 += w5[c * 5 + j] * xx;
            if (j >= 2) a3 += w3[c * 3 + (j - 2)] * xx;
        }
        xv[i] = xx; t3v[i] = a3; t5v[i] = a5;
    }

    float u0[2], u1[2], v[2];
    __nv_bfloat16 h, lo;
    u0[0] = xv[0] - t3v[0]; u0[1] = xv[1] - t3v[1];
    u1[0] = xv[0] - t5v[0]; u1[1] = xv[1] - t5v[1];
    routing2(u0, u1, v, red);
    bsplit(v[0], h, lo);
    g_Xs_hi[(size_t)row * DD + tid] = h;  g_Xs_lo[(size_t)row * DD + tid] = lo;
    bsplit(v[1], h, lo);
    g_Xs_hi[(size_t)row * DD + tid + 256] = h;  g_Xs_lo[(size_t)row * DD + tid + 256] = lo;

    u0[0] = t3v[0]; u0[1] = t3v[1];
    u1[0] = t5v[0]; u1[1] = t5v[1];
    routing2(u0, u1, v, red);
    bsplit(v[0], h, lo);
    g_Xt_hi[(size_t)row * DD + tid] = h;  g_Xt_lo[(size_t)row * DD + tid] = lo;
    bsplit(v[1], h, lo);
    g_Xt_hi[(size_t)row * DD + tid + 256] = h;  g_Xt_lo[(size_t)row * DD + tid + 256] = lo;
}

// ---------------------------------------------------------------------------
// W split kernel (512*1024 = 524288 elems)
// ---------------------------------------------------------------------------
__global__ void wsplit_kernel(const float* __restrict__ W) {
    int i = blockIdx.x * 256 + threadIdx.x;
    __nv_bfloat16 h, l;
    bsplit(W[i], h, l);
    g_W_hi[i] = h;
    g_W_lo[i] = l;
}

// ---------------------------------------------------------------------------
// attention: flash, bf16 3-pass m16n8k16, 32x32 tiles, grid=(64, 8, 2)
// ---------------------------------------------------------------------------
__global__ void __launch_bounds__(256, 1) attn_kernel() {
    extern __shared__ char smraw[];
    __nv_bfloat16* Qhi = (__nv_bfloat16*)(smraw + OFF_QHI);
    __nv_bfloat16* Qlo = (__nv_bfloat16*)(smraw + OFF_QLO);
    __nv_bfloat16* Khi = (__nv_bfloat16*)(smraw + OFF_KHI);
    __nv_bfloat16* Klo = (__nv_bfloat16*)(smraw + OFF_KLO);
    __nv_bfloat16* Phi = (__nv_bfloat16*)(smraw + OFF_PHI);
    __nv_bfloat16* Plo = (__nv_bfloat16*)(smraw + OFF_PLO);
    float* redm   = (float*)(smraw + OFF_RED);        // 128
    float* redl   = redm + 128;                       // 128
    float* m_s    = redl + 128;                       // 32
    float* l_s    = m_s + 32;                         // 32
    float* corr_s = l_s + 32;                         // 32

    int zb = blockIdx.z;
    const __nv_bfloat16* Xhi = (zb ? g_Xt_hi : g_Xs_hi) + (size_t)blockIdx.y * LQ * DD;
    const __nv_bfloat16* Xlo = (zb ? g_Xt_lo : g_Xs_lo) + (size_t)blockIdx.y * LQ * DD;
    int n = blockIdx.y;
    int qb = blockIdx.x;
    int tid = threadIdx.x;
    int w = tid >> 5, lane = tid & 31;
    int g4 = lane >> 2, tig = lane & 3, lane7 = lane & 7;
    int q0 = qb * 32;
    int rg = w & 1, cg = w >> 1;

    unsigned sb = (unsigned)__cvta_generic_to_shared(smraw);

    // per-lane ldmatrix pointer templates (byte offsets)
    int lrow = lane7 + ((lane >> 3) & 1) * 8;        // row within 16-row tile pair
    int lk8b = (lane >> 4) * 16;                     // +8 elems for tiles 2,3 of x4
    int bk8b = ((lane >> 3) & 1) * 16;               // +8 elems for tile 1 of x2

    unsigned aQhi = sb + OFF_QHI + (unsigned)((rg * 16 + lrow) * KQS * 2) + lk8b;
    unsigned aQlo = sb + OFF_QLO + (unsigned)((rg * 16 + lrow) * KQS * 2) + lk8b;
    unsigned bKhi = sb + OFF_KHI + (unsigned)((cg * 8 + lane7) * KQS * 2) + bk8b;
    unsigned bKlo = sb + OFF_KLO + (unsigned)((cg * 8 + lane7) * KQS * 2) + bk8b;
    unsigned aPhi = sb + OFF_PHI + (unsigned)((rg * 16 + lrow) * PS2 * 2) + lk8b;
    unsigned aPlo = sb + OFF_PLO + (unsigned)((rg * 16 + lrow) * PS2 * 2) + lk8b;
    unsigned bVhi = sb + OFF_KHI + (unsigned)(lrow * KQS * 2) + (unsigned)(cg * 256);
    unsigned bVlo = sb + OFF_KLO + (unsigned)(lrow * KQS * 2) + (unsigned)(cg * 256);

    // load Q tile (hi+lo)
    #pragma unroll
    for (int i0 = 0; i0 < 8; i0++) {
        int i = tid + i0 * 256;
        int r = i >> 6, c8 = (i & 63) << 3;
        *(uint4*)&Qhi[r * KQS + c8] = *(const uint4*)&Xhi[(size_t)(q0 + r) * DD + c8];
        *(uint4*)&Qlo[r * KQS + c8] = *(const uint4*)&Xlo[(size_t)(q0 + r) * DD + c8];
    }
    if (tid < 32) { m_s[tid] = -3.0e30f; l_s[tid] = 0.f; }

    float acc[16][4];
    #pragma unroll
    for (int i = 0; i < 16; i++) { acc[i][0] = acc[i][1] = acc[i][2] = acc[i][3] = 0.f; }

    int par0 = (rg * 16 + g4) * PS2;
    int par1 = (rg * 16 + g4 + 8) * PS2;
    int pc = cg * 8 + 2 * tig;

    for (int kb = 0; kb <= qb; kb++) {
        __syncthreads();                         // S1: prev PV reads of K/P done
        #pragma unroll
        for (int i0 = 0; i0 < 8; i0++) {
            int i = tid + i0 * 256;
            int r = i >> 6, c8 = (i & 63) << 3;
            *(uint4*)&Khi[r * KQS + c8] = *(const uint4*)&Xhi[(size_t)(kb * 32 + r) * DD + c8];
            *(uint4*)&Klo[r * KQS + c8] = *(const uint4*)&Xlo[(size_t)(kb * 32 + r) * DD + c8];
        }
        __syncthreads();                         // S2: K tile ready

        // --- scores: S = Q K^T, bf16 3-pass, 32 k16-steps ---
        float sc[4] = {0.f, 0.f, 0.f, 0.f};
        #pragma unroll 8
        for (int ks2 = 0; ks2 < 32; ks2++) {
            unsigned o = ks2 * 32;
            unsigned ah[4], al[4], bh[2], bl[2];
            ldmx4(ah, aQhi + o);
            ldmx4(al, aQlo + o);
            ldmx2(bh, bKhi + o);
            ldmx2(bl, bKlo + o);
            mma_bf16(sc, ah, bh);
            mma_bf16(sc, ah, bl);
            mma_bf16(sc, al, bh);
        }
        // bias + causal mask
        int r0 = q0 + rg * 16 + g4, r1 = r0 + 8;
        int c0 = kb * 32 + cg * 8 + 2 * tig, c1 = c0 + 1;
        sc[0] = (r0 >= c0) ? sc[0] - DECAYF * (float)(r0 - c0) : -3.0e30f;
        sc[1] = (r0 >= c1) ? sc[1] - DECAYF * (float)(r0 - c1) : -3.0e30f;
        sc[2] = (r1 >= c0) ? sc[2] - DECAYF * (float)(r1 - c0) : -3.0e30f;
        sc[3] = (r1 >= c1) ? sc[3] - DECAYF * (float)(r1 - c1) : -3.0e30f;

        // warp-level row max over this warp's 8 cols
        float m0 = fmaxf(sc[0], sc[1]);
        float m1 = fmaxf(sc[2], sc[3]);
        m0 = fmaxf(m0, __shfl_xor_sync(0xffffffffu, m0, 1));
        m0 = fmaxf(m0, __shfl_xor_sync(0xffffffffu, m0, 2));
        m1 = fmaxf(m1, __shfl_xor_sync(0xffffffffu, m1, 1));
        m1 = fmaxf(m1, __shfl_xor_sync(0xffffffffu, m1, 2));
        if (tig == 0) {
            redm[cg * 32 + rg * 16 + g4]     = m0;
            redm[cg * 32 + rg * 16 + g4 + 8] = m1;
        }
        __syncthreads();                         // S3: redm ready
        if (w == 0) {
            int r = lane;
            float tm = fmaxf(fmaxf(redm[r], redm[32 + r]), fmaxf(redm[64 + r], redm[96 + r]));
            float mo = m_s[r];
            float mn = fmaxf(mo, tm);
            m_s[r] = mn;
            corr_s[r] = __expf(mo - mn);
        }
        __syncthreads();                         // S4: m_s/corr_s ready

        // P = exp(S - m) -> split to bf16 hi/lo in smem; partial row sums
        {
            float mn0 = m_s[rg * 16 + g4];
            float mn1 = m_s[rg * 16 + g4 + 8];
            float p0 = __expf(sc[0] - mn0);
            float p1 = __expf(sc[1] - mn0);
            float p2 = __expf(sc[2] - mn1);
            float p3 = __expf(sc[3] - mn1);
            __nv_bfloat16 h0, l0, h1, l1;
            bsplit(p0, h0, l0); bsplit(p1, h1, l1);
            *(unsigned*)&Phi[par0 + pc] = pack2(h0, h1);
            *(unsigned*)&Plo[par0 + pc] = pack2(l0, l1);
            bsplit(p2, h0, l0); bsplit(p3, h1, l1);
            *(unsigned*)&Phi[par1 + pc] = pack2(h0, h1);
            *(unsigned*)&Plo[par1 + pc] = pack2(l0, l1);
            float s0 = p0 + p1, s1 = p2 + p3;
            s0 += __shfl_xor_sync(0xffffffffu, s0, 1);
            s0 += __shfl_xor_sync(0xffffffffu, s0, 2);
            s1 += __shfl_xor_sync(0xffffffffu, s1, 1);
            s1 += __shfl_xor_sync(0xffffffffu, s1, 2);
            if (tig == 0) {
                redl[cg * 32 + rg * 16 + g4]     = s0;
                redl[cg * 32 + rg * 16 + g4 + 8] = s1;
            }
        }
        __syncthreads();                         // S5: P + redl ready
        if (w == 0) {
            int r = lane;
            l_s[r] = l_s[r] * corr_s[r] + redl[r] + redl[32 + r] + redl[64 + r] + redl[96 + r];
        }

        // --- PV: O += P V, bf16 3-pass ---
        float cr0 = corr_s[rg * 16 + g4];
        float cr1 = corr_s[rg * 16 + g4 + 8];
        #pragma unroll
        for (int nf = 0; nf < 16; nf++) {
            acc[nf][0] *= cr0; acc[nf][1] *= cr0;
            acc[nf][2] *= cr1; acc[nf][3] *= cr1;
        }
        #pragma unroll
        for (int ks2 = 0; ks2 < 2; ks2++) {
            unsigned ah[4], al[4];
            ldmx4(ah, aPhi + ks2 * 32);
            ldmx4(al, aPlo + ks2 * 32);
            unsigned vh = bVhi + (unsigned)(ks2 * 16 * KQS * 2);
            unsigned vl = bVlo + (unsigned)(ks2 * 16 * KQS * 2);
            #pragma unroll
            for (int nf = 0; nf < 16; nf++) {
                unsigned bh[2], bl[2];
                ldmx2t(bh, vh + nf * 16);
                ldmx2t(bl, vl + nf * 16);
                mma_bf16(acc[nf], ah, bh);
                mma_bf16(acc[nf], ah, bl);
                mma_bf16(acc[nf], al, bh);
            }
        }
    }
    __syncthreads();

    // epilogue: normalize + split to bf16 hi/lo cat planes
    float li0 = 1.f / l_s[rg * 16 + g4];
    float li1 = 1.f / l_s[rg * 16 + g4 + 8];
    size_t orow0 = (size_t)(n * LQ + q0 + rg * 16 + g4) * (2 * DD);
    size_t orow1 = orow0 + (size_t)8 * (2 * DD);
    #pragma unroll
    for (int nf = 0; nf < 16; nf++) {
        int col = zb * DD + cg * 128 + nf * 8 + 2 * tig;
        __nv_bfloat16 h0, l0, h1, l1;
        bsplit(acc[nf][0] * li0, h0, l0);
        bsplit(acc[nf][1] * li0, h1, l1);
        *(unsigned*)&g_cat_hi[orow0 + col] = pack2(h0, h1);
        *(unsigned*)&g_cat_lo[orow0 + col] = pack2(l0, l1);
        bsplit(acc[nf][2] * li1, h0, l0);
        bsplit(acc[nf][3] * li1, h1, l1);
        *(unsigned*)&g_cat_hi[orow1 + col] = pack2(h0, h1);
        *(unsigned*)&g_cat_lo[orow1 + col] = pack2(l0, l1);
    }
}

// ---------------------------------------------------------------------------
// fusion: out[16384,512] = cat[16384,1024] @ W[512,1024]^T + bias, bf16 3-pass
// 64x64 tiles, k-chunk 64, grid=(256, 8)
// ---------------------------------------------------------------------------
__global__ void __launch_bounds__(256) fusion_kernel(const float* __restrict__ bias,
                                                     float* __restrict__ out) {
    __shared__ __nv_bfloat16 Ahi[64 * 72], Alo[64 * 72], Bhi[64 * 72], Blo[64 * 72];
    int bm = blockIdx.x * 64;
    int bn = blockIdx.y * 64;
    int tid = threadIdx.x;
    int w = tid >> 5, lane = tid & 31;
    int g4 = lane >> 2, tig = lane & 3, lane7 = lane & 7;
    int rg = w & 3, cg = w >> 2;
    int lrow = lane7 + ((lane >> 3) & 1) * 8;
    int lk8b = (lane >> 4) * 16;
    int bk8b = ((lane >> 3) & 1) * 16;

    unsigned ahiB = (unsigned)__cvta_generic_to_shared(Ahi) + (unsigned)((rg * 16 + lrow) * 144) + lk8b;
    unsigned aloB = (unsigned)__cvta_generic_to_shared(Alo) + (unsigned)((rg * 16 + lrow) * 144) + lk8b;
    unsigned bhiB = (unsigned)__cvta_generic_to_shared(Bhi) + (unsigned)((cg * 32 + lane7) * 144) + bk8b;
    unsigned bloB = (unsigned)__cvta_generic_to_shared(Blo) + (unsigned)((cg * 32 + lane7) * 144) + bk8b;

    float acc[4][4];
    #pragma unroll
    for (int i = 0; i < 4; i++) { acc[i][0] = acc[i][1] = acc[i][2] = acc[i][3] = 0.f; }

    for (int kc = 0; kc < 16; kc++) {
        __syncthreads();
        #pragma unroll
        for (int i0 = 0; i0 < 2; i0++) {
            int idx = tid + i0 * 256;           // 0..511
            int r = idx >> 3, c8 = (idx & 7) << 3;
            *(uint4*)&Ahi[r * 72 + c8] = *(const uint4*)&g_cat_hi[(size_t)(bm + r) * 1024 + kc * 64 + c8];
            *(uint4*)&Alo[r * 72 + c8] = *(const uint4*)&g_cat_lo[(size_t)(bm + r) * 1024 + kc * 64 + c8];
            *(uint4*)&Bhi[r * 72 + c8] = *(const uint4*)&g_W_hi[(size_t)(bn + r) * 1024 + kc * 64 + c8];
            *(uint4*)&Blo[r * 72 + c8] = *(const uint4*)&g_W_lo[(size_t)(bn + r) * 1024 + kc * 64 + c8];
        }
        __syncthreads();
        #pragma unroll
        for (int ks2 = 0; ks2 < 4; ks2++) {
            unsigned o = ks2 * 32;
            unsigned ah[4], al[4];
            ldmx4(ah, ahiB + o);
            ldmx4(al, aloB + o);
            #pragma unroll
            for (int nf = 0; nf < 4; nf++) {
                unsigned bh[2], bl[2];
                ldmx2(bh, bhiB + (unsigned)(nf * 1152) + o);   // 8 rows * 144B
                ldmx2(bl, bloB + (unsigned)(nf * 1152) + o);
                mma_bf16(acc[nf], ah, bh);
                mma_bf16(acc[nf], ah, bl);
                mma_bf16(acc[nf], al, bh);
            }
        }
    }

    int orow0 = bm + rg * 16 + g4, orow1 = orow0 + 8;
    #pragma unroll
    for (int nf = 0; nf < 4; nf++) {
        int col = bn + cg * 32 + nf * 8 + 2 * tig;
        float b0v = bias[col], b1v = bias[col + 1];
        *(float2*)&out[(size_t)orow0 * 512 + col] = make_float2(acc[nf][0] + b0v, acc[nf][1] + b1v);
        *(float2*)&out[(size_t)orow1 * 512 + col] = make_float2(acc[nf][2] + b0v, acc[nf][3] + b1v);
    }
}

// ---------------------------------------------------------------------------
extern "C" void kernel_launch(void* const* d_in, const int* in_sizes, int n_in,
                              void* d_out, int out_size) {
    const float* x  = (const float*)d_in[0];
    const float* w3 = (const float*)d_in[1];
    const float* w5 = (const float*)d_in[2];
    const float* fw = (const float*)d_in[3];
    const float* fb = (const float*)d_in[4];
    float* out = (float*)d_out;

    prep_kernel<<<NB * LQ, 256>>>(x, w3, w5);
    wsplit_kernel<<<(DD * 2 * DD) / 256, 256>>>(fw);

    cudaFuncSetAttribute(attn_kernel,
                         cudaFuncAttributeMaxDynamicSharedMemorySize, SMEM_ATTN);
    dim3 ga(LQ / 32, NB, 2);
    attn_kernel<<<ga, 256, SMEM_ATTN>>>();

    dim3 gf((NB * LQ) / 64, DD / 64);
    fusion_kernel<<<gf, 256>>>(fb, out);
}

// round 8
// speedup vs baseline: 5.3634x; 3.1692x over previous
#include <cuda_runtime.h>
#include <cuda_bf16.h>
#include <math.h>

#define NB 8
#define LQ 2048
#define DD 512
#define DECAYF 0.2f
#define WTILES 4     // window: keep current + 4 previous 32-row tiles (tail mass < 1e-10)
#define KQS 520      // K/Q smem tile stride in bf16 elems
#define PS2 40       // P tile stride in bf16 elems

// smem byte offsets for attn kernel
#define OFF_QHI 0
#define OFF_QLO 33280
#define OFF_KHI 66560
#define OFF_KLO 99840
#define OFF_PHI 133120
#define OFF_PLO 135680
#define OFF_RED 138240
#define SMEM_ATTN (OFF_RED + 1408)

// Scratch (device globals: allocation-free per harness rules)
__device__ __nv_bfloat16 g_Xs_hi[NB * LQ * DD];
__device__ __nv_bfloat16 g_Xs_lo[NB * LQ * DD];
__device__ __nv_bfloat16 g_Xt_hi[NB * LQ * DD];
__device__ __nv_bfloat16 g_Xt_lo[NB * LQ * DD];
__device__ __nv_bfloat16 g_cat_hi[NB * LQ * 2 * DD];
__device__ __nv_bfloat16 g_cat_lo[NB * LQ * 2 * DD];
__device__ __nv_bfloat16 g_W_hi[DD * 2 * DD];
__device__ __nv_bfloat16 g_W_lo[DD * 2 * DD];

// ---------------------------------------------------------------------------
// mma / ldmatrix helpers
// ---------------------------------------------------------------------------
__device__ __forceinline__ void ldmx4(unsigned* r, unsigned a) {
    asm volatile("ldmatrix.sync.aligned.m8n8.x4.shared.b16 {%0,%1,%2,%3}, [%4];"
        : "=r"(r[0]), "=r"(r[1]), "=r"(r[2]), "=r"(r[3]) : "r"(a));
}
__device__ __forceinline__ void ldmx2(unsigned* r, unsigned a) {
    asm volatile("ldmatrix.sync.aligned.m8n8.x2.shared.b16 {%0,%1}, [%2];"
        : "=r"(r[0]), "=r"(r[1]) : "r"(a));
}
__device__ __forceinline__ void ldmx2t(unsigned* r, unsigned a) {
    asm volatile("ldmatrix.sync.aligned.m8n8.x2.trans.shared.b16 {%0,%1}, [%2];"
        : "=r"(r[0]), "=r"(r[1]) : "r"(a));
}
__device__ __forceinline__ void mma_bf16(float* c, const unsigned* a, const unsigned* b) {
    asm volatile("mma.sync.aligned.m16n8k16.row.col.f32.bf16.bf16.f32 "
        "{%0,%1,%2,%3}, {%4,%5,%6,%7}, {%8,%9}, {%0,%1,%2,%3};"
        : "+f"(c[0]), "+f"(c[1]), "+f"(c[2]), "+f"(c[3])
        : "r"(a[0]), "r"(a[1]), "r"(a[2]), "r"(a[3]), "r"(b[0]), "r"(b[1]));
}
__device__ __forceinline__ void bsplit(float x, __nv_bfloat16& h, __nv_bfloat16& l) {
    h = __float2bfloat16(x);
    l = __float2bfloat16(x - __bfloat162float(h));
}
__device__ __forceinline__ unsigned pack2(__nv_bfloat16 a, __nv_bfloat16 b) {
    return ((unsigned)__bfloat16_as_ushort(b) << 16) | (unsigned)__bfloat16_as_ushort(a);
}
__device__ __forceinline__ float warpSum(float v) {
    #pragma unroll
    for (int o = 16; o > 0; o >>= 1) v += __shfl_xor_sync(0xffffffffu, v, o);
    return v;
}

// ---------------------------------------------------------------------------
// Warp-level routing: 16 channels per lane, shuffle reductions, no barriers
// ---------------------------------------------------------------------------
__device__ __forceinline__ void routing16(const float* u0, const float* u1, float* vout) {
    float b0 = 0.f, b1 = 0.f;
    #pragma unroll
    for (int it = 0; it < 3; it++) {
        float mx = fmaxf(b0, b1);
        float e0 = __expf(b0 - mx), e1 = __expf(b1 - mx);
        float inv = 1.f / (e0 + e1);
        float c0 = e0 * inv, c1 = e1 * inv;
        float loc = 0.f;
        #pragma unroll
        for (int i = 0; i < 16; i++) {
            float s = c0 * u0[i] + c1 * u1[i];
            vout[i] = s;
            loc = fmaf(s, s, loc);
        }
        float n2 = warpSum(loc);
        float nrm = sqrtf(n2);
        float scl = n2 / ((1.f + n2) * (nrm + 1e-9f));
        #pragma unroll
        for (int i = 0; i < 16; i++) vout[i] *= scl;
        if (it < 2) {
            float l0 = 0.f, l1 = 0.f;
            #pragma unroll
            for (int i = 0; i < 16; i++) {
                l0 = fmaf(u0[i], vout[i], l0);
                l1 = fmaf(u1[i], vout[i], l1);
            }
            b0 += warpSum(l0);
            b1 += warpSum(l1);
        }
    }
}

// ---------------------------------------------------------------------------
// Kernel 1: convs + routing, warp-per-row, writes bf16 hi/lo planes
// grid = 2048 blocks x 256 threads (8 warps = 8 rows per block)
// ---------------------------------------------------------------------------
__global__ void __launch_bounds__(256) prep_kernel(const float* __restrict__ x,
                                                   const float* __restrict__ w3,
                                                   const float* __restrict__ w5) {
    int wid = threadIdx.x >> 5, lane = threadIdx.x & 31;
    int row = blockIdx.x * 8 + wid;
    int n = row >> 11, l = row & 2047;
    const float* xb = x + (size_t)n * LQ * DD;

    float xv[16], t3[16], t5[16];
    #pragma unroll
    for (int i = 0; i < 16; i++) {
        int c = lane + 32 * i;
        float a3 = 0.f, a5 = 0.f, xx = 0.f;
        #pragma unroll
        for (int j = 0; j < 5; j++) {
            int ll = l - 4 + j;
            xx = (ll >= 0) ? __ldg(xb + (size_t)ll * DD + c) : 0.f;
            a5 = fmaf(w5[c * 5 + j], xx, a5);
            if (j >= 2) a3 = fmaf(w3[c * 3 + (j - 2)], xx, a3);
        }
        xv[i] = xx; t3[i] = a3; t5[i] = a5;
    }

    float u0[16], u1[16], v[16];
    __nv_bfloat16 h, lo;
    // seasonal: [x - t3, x - t5]
    #pragma unroll
    for (int i = 0; i < 16; i++) { u0[i] = xv[i] - t3[i]; u1[i] = xv[i] - t5[i]; }
    routing16(u0, u1, v);
    #pragma unroll
    for (int i = 0; i < 16; i++) {
        int c = lane + 32 * i;
        bsplit(v[i], h, lo);
        g_Xs_hi[(size_t)row * DD + c] = h;
        g_Xs_lo[(size_t)row * DD + c] = lo;
    }
    // trend: [t3, t5]
    routing16(t3, t5, v);
    #pragma unroll
    for (int i = 0; i < 16; i++) {
        int c = lane + 32 * i;
        bsplit(v[i], h, lo);
        g_Xt_hi[(size_t)row * DD + c] = h;
        g_Xt_lo[(size_t)row * DD + c] = lo;
    }
}

// ---------------------------------------------------------------------------
// W split kernel
// ---------------------------------------------------------------------------
__global__ void wsplit_kernel(const float* __restrict__ W) {
    int i = blockIdx.x * 256 + threadIdx.x;
    __nv_bfloat16 h, l;
    bsplit(W[i], h, l);
    g_W_hi[i] = h;
    g_W_lo[i] = l;
}

// ---------------------------------------------------------------------------
// attention: flash, bf16 3-pass m16n8k16, 32x32 tiles, WINDOWED (5 tiles)
// grid=(64, 8, 2), 256 threads
// ---------------------------------------------------------------------------
__global__ void __launch_bounds__(256, 1) attn_kernel() {
    extern __shared__ char smraw[];
    __nv_bfloat16* Qhi = (__nv_bfloat16*)(smraw + OFF_QHI);
    __nv_bfloat16* Qlo = (__nv_bfloat16*)(smraw + OFF_QLO);
    __nv_bfloat16* Khi = (__nv_bfloat16*)(smraw + OFF_KHI);
    __nv_bfloat16* Klo = (__nv_bfloat16*)(smraw + OFF_KLO);
    __nv_bfloat16* Phi = (__nv_bfloat16*)(smraw + OFF_PHI);
    __nv_bfloat16* Plo = (__nv_bfloat16*)(smraw + OFF_PLO);
    float* redm   = (float*)(smraw + OFF_RED);
    float* redl   = redm + 128;
    float* m_s    = redl + 128;
    float* l_s    = m_s + 32;
    float* corr_s = l_s + 32;

    int zb = blockIdx.z;
    const __nv_bfloat16* Xhi = (zb ? g_Xt_hi : g_Xs_hi) + (size_t)blockIdx.y * LQ * DD;
    const __nv_bfloat16* Xlo = (zb ? g_Xt_lo : g_Xs_lo) + (size_t)blockIdx.y * LQ * DD;
    int n = blockIdx.y;
    int qb = blockIdx.x;
    int tid = threadIdx.x;
    int w = tid >> 5, lane = tid & 31;
    int g4 = lane >> 2, tig = lane & 3, lane7 = lane & 7;
    int q0 = qb * 32;
    int rg = w & 1, cg = w >> 1;

    unsigned sb = (unsigned)__cvta_generic_to_shared(smraw);

    int lrow = lane7 + ((lane >> 3) & 1) * 8;
    int lk8b = (lane >> 4) * 16;
    int bk8b = ((lane >> 3) & 1) * 16;

    unsigned aQhi = sb + OFF_QHI + (unsigned)((rg * 16 + lrow) * KQS * 2) + lk8b;
    unsigned aQlo = sb + OFF_QLO + (unsigned)((rg * 16 + lrow) * KQS * 2) + lk8b;
    unsigned bKhi = sb + OFF_KHI + (unsigned)((cg * 8 + lane7) * KQS * 2) + bk8b;
    unsigned bKlo = sb + OFF_KLO + (unsigned)((cg * 8 + lane7) * KQS * 2) + bk8b;
    unsigned aPhi = sb + OFF_PHI + (unsigned)((rg * 16 + lrow) * PS2 * 2) + lk8b;
    unsigned aPlo = sb + OFF_PLO + (unsigned)((rg * 16 + lrow) * PS2 * 2) + lk8b;
    unsigned bVhi = sb + OFF_KHI + (unsigned)(lrow * KQS * 2) + (unsigned)(cg * 256);
    unsigned bVlo = sb + OFF_KLO + (unsigned)(lrow * KQS * 2) + (unsigned)(cg * 256);

    // load Q tile (hi+lo)
    #pragma unroll
    for (int i0 = 0; i0 < 8; i0++) {
        int i = tid + i0 * 256;
        int r = i >> 6, c8 = (i & 63) << 3;
        *(uint4*)&Qhi[r * KQS + c8] = *(const uint4*)&Xhi[(size_t)(q0 + r) * DD + c8];
        *(uint4*)&Qlo[r * KQS + c8] = *(const uint4*)&Xlo[(size_t)(q0 + r) * DD + c8];
    }
    if (tid < 32) { m_s[tid] = -3.0e30f; l_s[tid] = 0.f; }

    float acc[16][4];
    #pragma unroll
    for (int i = 0; i < 16; i++) { acc[i][0] = acc[i][1] = acc[i][2] = acc[i][3] = 0.f; }

    int par0 = (rg * 16 + g4) * PS2;
    int par1 = (rg * 16 + g4 + 8) * PS2;
    int pc = cg * 8 + 2 * tig;

    // windowed causal: keys beyond 4 tiles back carry softmax mass < 1e-10
    int kb0 = (qb >= WTILES) ? qb - WTILES : 0;
    for (int kb = kb0; kb <= qb; kb++) {
        __syncthreads();                         // S1: prev PV reads of K/P done
        #pragma unroll
        for (int i0 = 0; i0 < 8; i0++) {
            int i = tid + i0 * 256;
            int r = i >> 6, c8 = (i & 63) << 3;
            *(uint4*)&Khi[r * KQS + c8] = *(const uint4*)&Xhi[(size_t)(kb * 32 + r) * DD + c8];
            *(uint4*)&Klo[r * KQS + c8] = *(const uint4*)&Xlo[(size_t)(kb * 32 + r) * DD + c8];
        }
        __syncthreads();                         // S2: K tile ready

        // --- scores: S = Q K^T, bf16 3-pass ---
        float sc[4] = {0.f, 0.f, 0.f, 0.f};
        #pragma unroll 8
        for (int ks2 = 0; ks2 < 32; ks2++) {
            unsigned o = ks2 * 32;
            unsigned ah[4], al[4], bh[2], bl[2];
            ldmx4(ah, aQhi + o);
            ldmx4(al, aQlo + o);
            ldmx2(bh, bKhi + o);
            ldmx2(bl, bKlo + o);
            mma_bf16(sc, ah, bh);
            mma_bf16(sc, ah, bl);
            mma_bf16(sc, al, bh);
        }
        int r0 = q0 + rg * 16 + g4, r1 = r0 + 8;
        int c0 = kb * 32 + cg * 8 + 2 * tig, c1 = c0 + 1;
        sc[0] = (r0 >= c0) ? sc[0] - DECAYF * (float)(r0 - c0) : -3.0e30f;
        sc[1] = (r0 >= c1) ? sc[1] - DECAYF * (float)(r0 - c1) : -3.0e30f;
        sc[2] = (r1 >= c0) ? sc[2] - DECAYF * (float)(r1 - c0) : -3.0e30f;
        sc[3] = (r1 >= c1) ? sc[3] - DECAYF * (float)(r1 - c1) : -3.0e30f;

        float m0 = fmaxf(sc[0], sc[1]);
        float m1 = fmaxf(sc[2], sc[3]);
        m0 = fmaxf(m0, __shfl_xor_sync(0xffffffffu, m0, 1));
        m0 = fmaxf(m0, __shfl_xor_sync(0xffffffffu, m0, 2));
        m1 = fmaxf(m1, __shfl_xor_sync(0xffffffffu, m1, 1));
        m1 = fmaxf(m1, __shfl_xor_sync(0xffffffffu, m1, 2));
        if (tig == 0) {
            redm[cg * 32 + rg * 16 + g4]     = m0;
            redm[cg * 32 + rg * 16 + g4 + 8] = m1;
        }
        __syncthreads();                         // S3: redm ready
        if (w == 0) {
            int r = lane;
            float tm = fmaxf(fmaxf(redm[r], redm[32 + r]), fmaxf(redm[64 + r], redm[96 + r]));
            float mo = m_s[r];
            float mn = fmaxf(mo, tm);
            m_s[r] = mn;
            corr_s[r] = __expf(mo - mn);
        }
        __syncthreads();                         // S4: m_s/corr_s ready

        {
            float mn0 = m_s[rg * 16 + g4];
            float mn1 = m_s[rg * 16 + g4 + 8];
            float p0 = __expf(sc[0] - mn0);
            float p1 = __expf(sc[1] - mn0);
            float p2 = __expf(sc[2] - mn1);
            float p3 = __expf(sc[3] - mn1);
            __nv_bfloat16 h0, l0, h1, l1;
            bsplit(p0, h0, l0); bsplit(p1, h1, l1);
            *(unsigned*)&Phi[par0 + pc] = pack2(h0, h1);
            *(unsigned*)&Plo[par0 + pc] = pack2(l0, l1);
            bsplit(p2, h0, l0); bsplit(p3, h1, l1);
            *(unsigned*)&Phi[par1 + pc] = pack2(h0, h1);
            *(unsigned*)&Plo[par1 + pc] = pack2(l0, l1);
            float s0 = p0 + p1, s1 = p2 + p3;
            s0 += __shfl_xor_sync(0xffffffffu, s0, 1);
            s0 += __shfl_xor_sync(0xffffffffu, s0, 2);
            s1 += __shfl_xor_sync(0xffffffffu, s1, 1);
            s1 += __shfl_xor_sync(0xffffffffu, s1, 2);
            if (tig == 0) {
                redl[cg * 32 + rg * 16 + g4]     = s0;
                redl[cg * 32 + rg * 16 + g4 + 8] = s1;
            }
        }
        __syncthreads();                         // S5: P + redl ready
        if (w == 0) {
            int r = lane;
            l_s[r] = l_s[r] * corr_s[r] + redl[r] + redl[32 + r] + redl[64 + r] + redl[96 + r];
        }

        // --- PV: O += P V, bf16 3-pass ---
        float cr0 = corr_s[rg * 16 + g4];
        float cr1 = corr_s[rg * 16 + g4 + 8];
        #pragma unroll
        for (int nf = 0; nf < 16; nf++) {
            acc[nf][0] *= cr0; acc[nf][1] *= cr0;
            acc[nf][2] *= cr1; acc[nf][3] *= cr1;
        }
        #pragma unroll
        for (int ks2 = 0; ks2 < 2; ks2++) {
            unsigned ah[4], al[4];
            ldmx4(ah, aPhi + ks2 * 32);
            ldmx4(al, aPlo + ks2 * 32);
            unsigned vh = bVhi + (unsigned)(ks2 * 16 * KQS * 2);
            unsigned vl = bVlo + (unsigned)(ks2 * 16 * KQS * 2);
            #pragma unroll
            for (int nf = 0; nf < 16; nf++) {
                unsigned bh[2], bl[2];
                ldmx2t(bh, vh + nf * 16);
                ldmx2t(bl, vl + nf * 16);
                mma_bf16(acc[nf], ah, bh);
                mma_bf16(acc[nf], ah, bl);
                mma_bf16(acc[nf], al, bh);
            }
        }
    }
    __syncthreads();

    float li0 = 1.f / l_s[rg * 16 + g4];
    float li1 = 1.f / l_s[rg * 16 + g4 + 8];
    size_t orow0 = (size_t)(n * LQ + q0 + rg * 16 + g4) * (2 * DD);
    size_t orow1 = orow0 + (size_t)8 * (2 * DD);
    #pragma unroll
    for (int nf = 0; nf < 16; nf++) {
        int col = zb * DD + cg * 128 + nf * 8 + 2 * tig;
        __nv_bfloat16 h0, l0, h1, l1;
        bsplit(acc[nf][0] * li0, h0, l0);
        bsplit(acc[nf][1] * li0, h1, l1);
        *(unsigned*)&g_cat_hi[orow0 + col] = pack2(h0, h1);
        *(unsigned*)&g_cat_lo[orow0 + col] = pack2(l0, l1);
        bsplit(acc[nf][2] * li1, h0, l0);
        bsplit(acc[nf][3] * li1, h1, l1);
        *(unsigned*)&g_cat_hi[orow1 + col] = pack2(h0, h1);
        *(unsigned*)&g_cat_lo[orow1 + col] = pack2(l0, l1);
    }
}

// ---------------------------------------------------------------------------
// fusion: out = cat @ W^T + bias, bf16 3-pass, 64x64 tiles
// ---------------------------------------------------------------------------
__global__ void __launch_bounds__(256) fusion_kernel(const float* __restrict__ bias,
                                                     float* __restrict__ out) {
    __shared__ __nv_bfloat16 Ahi[64 * 72], Alo[64 * 72], Bhi[64 * 72], Blo[64 * 72];
    int bm = blockIdx.x * 64;
    int bn = blockIdx.y * 64;
    int tid = threadIdx.x;
    int w = tid >> 5, lane = tid & 31;
    int g4 = lane >> 2, tig = lane & 3, lane7 = lane & 7;
    int rg = w & 3, cg = w >> 2;
    int lrow = lane7 + ((lane >> 3) & 1) * 8;
    int lk8b = (lane >> 4) * 16;
    int bk8b = ((lane >> 3) & 1) * 16;

    unsigned ahiB = (unsigned)__cvta_generic_to_shared(Ahi) + (unsigned)((rg * 16 + lrow) * 144) + lk8b;
    unsigned aloB = (unsigned)__cvta_generic_to_shared(Alo) + (unsigned)((rg * 16 + lrow) * 144) + lk8b;
    unsigned bhiB = (unsigned)__cvta_generic_to_shared(Bhi) + (unsigned)((cg * 32 + lane7) * 144) + bk8b;
    unsigned bloB = (unsigned)__cvta_generic_to_shared(Blo) + (unsigned)((cg * 32 + lane7) * 144) + bk8b;

    float acc[4][4];
    #pragma unroll
    for (int i = 0; i < 4; i++) { acc[i][0] = acc[i][1] = acc[i][2] = acc[i][3] = 0.f; }

    for (int kc = 0; kc < 16; kc++) {
        __syncthreads();
        #pragma unroll
        for (int i0 = 0; i0 < 2; i0++) {
            int idx = tid + i0 * 256;
            int r = idx >> 3, c8 = (idx & 7) << 3;
            *(uint4*)&Ahi[r * 72 + c8] = *(const uint4*)&g_cat_hi[(size_t)(bm + r) * 1024 + kc * 64 + c8];
            *(uint4*)&Alo[r * 72 + c8] = *(const uint4*)&g_cat_lo[(size_t)(bm + r) * 1024 + kc * 64 + c8];
            *(uint4*)&Bhi[r * 72 + c8] = *(const uint4*)&g_W_hi[(size_t)(bn + r) * 1024 + kc * 64 + c8];
            *(uint4*)&Blo[r * 72 + c8] = *(const uint4*)&g_W_lo[(size_t)(bn + r) * 1024 + kc * 64 + c8];
        }
        __syncthreads();
        #pragma unroll
        for (int ks2 = 0; ks2 < 4; ks2++) {
            unsigned o = ks2 * 32;
            unsigned ah[4], al[4];
            ldmx4(ah, ahiB + o);
            ldmx4(al, aloB + o);
            #pragma unroll
            for (int nf = 0; nf < 4; nf++) {
                unsigned bh[2], bl[2];
                ldmx2(bh, bhiB + (unsigned)(nf * 1152) + o);
                ldmx2(bl, bloB + (unsigned)(nf * 1152) + o);
                mma_bf16(acc[nf], ah, bh);
                mma_bf16(acc[nf], ah, bl);
                mma_bf16(acc[nf], al, bh);
            }
        }
    }

    int orow0 = bm + rg * 16 + g4, orow1 = orow0 + 8;
    #pragma unroll
    for (int nf = 0; nf < 4; nf++) {
        int col = bn + cg * 32 + nf * 8 + 2 * tig;
        float b0v = bias[col], b1v = bias[col + 1];
        *(float2*)&out[(size_t)orow0 * 512 + col] = make_float2(acc[nf][0] + b0v, acc[nf][1] + b1v);
        *(float2*)&out[(size_t)orow1 * 512 + col] = make_float2(acc[nf][2] + b0v, acc[nf][3] + b1v);
    }
}

// ---------------------------------------------------------------------------
extern "C" void kernel_launch(void* const* d_in, const int* in_sizes, int n_in,
                              void* d_out, int out_size) {
    const float* x  = (const float*)d_in[0];
    const float* w3 = (const float*)d_in[1];
    const float* w5 = (const float*)d_in[2];
    const float* fw = (const float*)d_in[3];
    const float* fb = (const float*)d_in[4];
    float* out = (float*)d_out;

    prep_kernel<<<NB * LQ / 8, 256>>>(x, w3, w5);
    wsplit_kernel<<<(DD * 2 * DD) / 256, 256>>>(fw);

    cudaFuncSetAttribute(attn_kernel,
                         cudaFuncAttributeMaxDynamicSharedMemorySize, SMEM_ATTN);
    dim3 ga(LQ / 32, NB, 2);
    attn_kernel<<<ga, 256, SMEM_ATTN>>>();

    dim3 gf((NB * LQ) / 64, DD / 64);
    fusion_kernel<<<gf, 256>>>(fb, out);
}

// round 10
// speedup vs baseline: 6.1849x; 1.1532x over previous
#include <cuda_runtime.h>
#include <cuda_bf16.h>
#include <math.h>

#define NB 8
#define LQ 2048
#define DD 512
#define DECAYF 0.2f
#define WTILES 2     // window: current + 2 previous 32-row tiles (tail mass < 3.4e-5)
#define KQS 520
#define PS2 40

// attn smem offsets
#define OFF_QHI 0
#define OFF_QLO 33280
#define OFF_KHI 66560
#define OFF_KLO 99840
#define OFF_PHI 133120
#define OFF_PLO 135680
#define OFF_RED 138240
#define SMEM_ATTN (OFF_RED + 512)

// Scratch (device globals: allocation-free per harness rules)
__device__ __nv_bfloat16 g_Xs_hi[NB * LQ * DD];
__device__ __nv_bfloat16 g_Xs_lo[NB * LQ * DD];
__device__ __nv_bfloat16 g_Xt_hi[NB * LQ * DD];
__device__ __nv_bfloat16 g_Xt_lo[NB * LQ * DD];
__device__ __nv_bfloat16 g_cat_hi[NB * LQ * 2 * DD];
__device__ __nv_bfloat16 g_cat_lo[NB * LQ * 2 * DD];
__device__ __nv_bfloat16 g_W_hi[DD * 2 * DD];
__device__ __nv_bfloat16 g_W_lo[DD * 2 * DD];

// ---------------------------------------------------------------------------
// mma / ldmatrix helpers (legacy mma.sync — tcgen05 is not available on this
// toolchain target; ptxas rejects tcgen05.* for sm_103 non-'a')
// ---------------------------------------------------------------------------
__device__ __forceinline__ void ldmx4(unsigned* r, unsigned a) {
    asm volatile("ldmatrix.sync.aligned.m8n8.x4.shared.b16 {%0,%1,%2,%3}, [%4];"
        : "=r"(r[0]), "=r"(r[1]), "=r"(r[2]), "=r"(r[3]) : "r"(a));
}
__device__ __forceinline__ void ldmx2(unsigned* r, unsigned a) {
    asm volatile("ldmatrix.sync.aligned.m8n8.x2.shared.b16 {%0,%1}, [%2];"
        : "=r"(r[0]), "=r"(r[1]) : "r"(a));
}
__device__ __forceinline__ void ldmx2t(unsigned* r, unsigned a) {
    asm volatile("ldmatrix.sync.aligned.m8n8.x2.trans.shared.b16 {%0,%1}, [%2];"
        : "=r"(r[0]), "=r"(r[1]) : "r"(a));
}
__device__ __forceinline__ void mma_bf16(float* c, const unsigned* a, const unsigned* b) {
    asm volatile("mma.sync.aligned.m16n8k16.row.col.f32.bf16.bf16.f32 "
        "{%0,%1,%2,%3}, {%4,%5,%6,%7}, {%8,%9}, {%0,%1,%2,%3};"
        : "+f"(c[0]), "+f"(c[1]), "+f"(c[2]), "+f"(c[3])
        : "r"(a[0]), "r"(a[1]), "r"(a[2]), "r"(a[3]), "r"(b[0]), "r"(b[1]));
}
__device__ __forceinline__ void bsplit(float x, __nv_bfloat16& h, __nv_bfloat16& l) {
    h = __float2bfloat16(x);
    l = __float2bfloat16(x - __bfloat162float(h));
}
__device__ __forceinline__ unsigned pack2(__nv_bfloat16 a, __nv_bfloat16 b) {
    return ((unsigned)__bfloat16_as_ushort(b) << 16) | (unsigned)__bfloat16_as_ushort(a);
}
__device__ __forceinline__ float warpSum(float v) {
    #pragma unroll
    for (int o = 16; o > 0; o >>= 1) v += __shfl_xor_sync(0xffffffffu, v, o);
    return v;
}

// ---------------------------------------------------------------------------
// Warp-level routing
// ---------------------------------------------------------------------------
__device__ __forceinline__ void routing16(const float* u0, const float* u1, float* vout) {
    float b0 = 0.f, b1 = 0.f;
    #pragma unroll
    for (int it = 0; it < 3; it++) {
        float mx = fmaxf(b0, b1);
        float e0 = __expf(b0 - mx), e1 = __expf(b1 - mx);
        float inv = 1.f / (e0 + e1);
        float c0 = e0 * inv, c1 = e1 * inv;
        float loc = 0.f;
        #pragma unroll
        for (int i = 0; i < 16; i++) {
            float s = c0 * u0[i] + c1 * u1[i];
            vout[i] = s;
            loc = fmaf(s, s, loc);
        }
        float n2 = warpSum(loc);
        float nrm = sqrtf(n2);
        float scl = n2 / ((1.f + n2) * (nrm + 1e-9f));
        #pragma unroll
        for (int i = 0; i < 16; i++) vout[i] *= scl;
        if (it < 2) {
            float l0 = 0.f, l1 = 0.f;
            #pragma unroll
            for (int i = 0; i < 16; i++) {
                l0 = fmaf(u0[i], vout[i], l0);
                l1 = fmaf(u1[i], vout[i], l1);
            }
            b0 += warpSum(l0);
            b1 += warpSum(l1);
        }
    }
}

// ---------------------------------------------------------------------------
// Kernel 1: convs + routing, warp-per-row
// ---------------------------------------------------------------------------
__global__ void __launch_bounds__(256) prep_kernel(const float* __restrict__ x,
                                                   const float* __restrict__ w3,
                                                   const float* __restrict__ w5) {
    int wid = threadIdx.x >> 5, lane = threadIdx.x & 31;
    int row = blockIdx.x * 8 + wid;
    int n = row >> 11, l = row & 2047;
    const float* xb = x + (size_t)n * LQ * DD;

    float xv[16], t3[16], t5[16];
    #pragma unroll
    for (int i = 0; i < 16; i++) {
        int c = lane + 32 * i;
        float a3 = 0.f, a5 = 0.f, xx = 0.f;
        #pragma unroll
        for (int j = 0; j < 5; j++) {
            int ll = l - 4 + j;
            xx = (ll >= 0) ? __ldg(xb + (size_t)ll * DD + c) : 0.f;
            a5 = fmaf(w5[c * 5 + j], xx, a5);
            if (j >= 2) a3 = fmaf(w3[c * 3 + (j - 2)], xx, a3);
        }
        xv[i] = xx; t3[i] = a3; t5[i] = a5;
    }

    float u0[16], u1[16], v[16];
    __nv_bfloat16 h, lo;
    #pragma unroll
    for (int i = 0; i < 16; i++) { u0[i] = xv[i] - t3[i]; u1[i] = xv[i] - t5[i]; }
    routing16(u0, u1, v);
    #pragma unroll
    for (int i = 0; i < 16; i++) {
        int c = lane + 32 * i;
        bsplit(v[i], h, lo);
        g_Xs_hi[(size_t)row * DD + c] = h;
        g_Xs_lo[(size_t)row * DD + c] = lo;
    }
    routing16(t3, t5, v);
    #pragma unroll
    for (int i = 0; i < 16; i++) {
        int c = lane + 32 * i;
        bsplit(v[i], h, lo);
        g_Xt_hi[(size_t)row * DD + c] = h;
        g_Xt_lo[(size_t)row * DD + c] = lo;
    }
}

__global__ void wsplit_kernel(const float* __restrict__ W) {
    int i = blockIdx.x * 256 + threadIdx.x;
    __nv_bfloat16 h, l;
    bsplit(W[i], h, l);
    g_W_hi[i] = h;
    g_W_lo[i] = l;
}

// ---------------------------------------------------------------------------
// attention: windowed flash, bf16 3-pass, NO online max (scores bounded <= 1,
// exp(s) in [3e-10, 2.72] -> fixed-shift softmax is exact in fp32).
// grid=(64, 8, 2), 256 threads, 3 syncs per kb-iteration.
// ---------------------------------------------------------------------------
__global__ void __launch_bounds__(256, 1) attn_kernel() {
    extern __shared__ char smraw[];
    __nv_bfloat16* Qhi = (__nv_bfloat16*)(smraw + OFF_QHI);
    __nv_bfloat16* Qlo = (__nv_bfloat16*)(smraw + OFF_QLO);
    __nv_bfloat16* Khi = (__nv_bfloat16*)(smraw + OFF_KHI);
    __nv_bfloat16* Klo = (__nv_bfloat16*)(smraw + OFF_KLO);
    __nv_bfloat16* Phi = (__nv_bfloat16*)(smraw + OFF_PHI);
    __nv_bfloat16* Plo = (__nv_bfloat16*)(smraw + OFF_PLO);
    float* redl = (float*)(smraw + OFF_RED);   // 4 x 32

    int zb = blockIdx.z;
    const __nv_bfloat16* Xhi = (zb ? g_Xt_hi : g_Xs_hi) + (size_t)blockIdx.y * LQ * DD;
    const __nv_bfloat16* Xlo = (zb ? g_Xt_lo : g_Xs_lo) + (size_t)blockIdx.y * LQ * DD;
    int n = blockIdx.y;
    int qb = blockIdx.x;
    int tid = threadIdx.x;
    int w = tid >> 5, lane = tid & 31;
    int g4 = lane >> 2, tig = lane & 3, lane7 = lane & 7;
    int q0 = qb * 32;
    int rg = w & 1, cg = w >> 1;

    unsigned sb = (unsigned)__cvta_generic_to_shared(smraw);
    int lrow = lane7 + ((lane >> 3) & 1) * 8;
    int lk8b = (lane >> 4) * 16;
    int bk8b = ((lane >> 3) & 1) * 16;

    unsigned aQhi = sb + OFF_QHI + (unsigned)((rg * 16 + lrow) * KQS * 2) + lk8b;
    unsigned aQlo = sb + OFF_QLO + (unsigned)((rg * 16 + lrow) * KQS * 2) + lk8b;
    unsigned bKhi = sb + OFF_KHI + (unsigned)((cg * 8 + lane7) * KQS * 2) + bk8b;
    unsigned bKlo = sb + OFF_KLO + (unsigned)((cg * 8 + lane7) * KQS * 2) + bk8b;
    unsigned aPhi = sb + OFF_PHI + (unsigned)((rg * 16 + lrow) * PS2 * 2) + lk8b;
    unsigned aPlo = sb + OFF_PLO + (unsigned)((rg * 16 + lrow) * PS2 * 2) + lk8b;
    unsigned bVhi = sb + OFF_KHI + (unsigned)(lrow * KQS * 2) + (unsigned)(cg * 256);
    unsigned bVlo = sb + OFF_KLO + (unsigned)(lrow * KQS * 2) + (unsigned)(cg * 256);

    // load Q tile (hi+lo)
    #pragma unroll
    for (int i0 = 0; i0 < 8; i0++) {
        int i = tid + i0 * 256;
        int r = i >> 6, c8 = (i & 63) << 3;
        *(uint4*)&Qhi[r * KQS + c8] = *(const uint4*)&Xhi[(size_t)(q0 + r) * DD + c8];
        *(uint4*)&Qlo[r * KQS + c8] = *(const uint4*)&Xlo[(size_t)(q0 + r) * DD + c8];
    }

    float acc[16][4];
    #pragma unroll
    for (int i = 0; i < 16; i++) { acc[i][0] = acc[i][1] = acc[i][2] = acc[i][3] = 0.f; }
    float lsum0 = 0.f, lsum1 = 0.f;   // running softmax denominators (fixed shift)

    int par0 = (rg * 16 + g4) * PS2;
    int par1 = (rg * 16 + g4 + 8) * PS2;
    int pc = cg * 8 + 2 * tig;

    int kb0 = (qb >= WTILES) ? qb - WTILES : 0;
    for (int kb = kb0; kb <= qb; kb++) {
        __syncthreads();                      // S1: prev iter's PV reads of K/P done
        #pragma unroll
        for (int i0 = 0; i0 < 8; i0++) {
            int i = tid + i0 * 256;
            int r = i >> 6, c8 = (i & 63) << 3;
            *(uint4*)&Khi[r * KQS + c8] = *(const uint4*)&Xhi[(size_t)(kb * 32 + r) * DD + c8];
            *(uint4*)&Klo[r * KQS + c8] = *(const uint4*)&Xlo[(size_t)(kb * 32 + r) * DD + c8];
        }
        __syncthreads();                      // S2: K tile ready

        // scores: S = Q K^T, bf16 3-pass
        float sc[4] = {0.f, 0.f, 0.f, 0.f};
        #pragma unroll 8
        for (int ks2 = 0; ks2 < 32; ks2++) {
            unsigned o = ks2 * 32;
            unsigned ah[4], al[4], bh[2], bl[2];
            ldmx4(ah, aQhi + o);
            ldmx4(al, aQlo + o);
            ldmx2(bh, bKhi + o);
            ldmx2(bl, bKlo + o);
            mma_bf16(sc, ah, bh);
            mma_bf16(sc, ah, bl);
            mma_bf16(sc, al, bh);
        }
        int r0 = q0 + rg * 16 + g4, r1 = r0 + 8;
        int c0 = kb * 32 + cg * 8 + 2 * tig, c1 = c0 + 1;

        // p = exp(s - 0.2*d) with causal mask; no max subtraction needed
        float p0 = (r0 >= c0) ? __expf(sc[0] - DECAYF * (float)(r0 - c0)) : 0.f;
        float p1 = (r0 >= c1) ? __expf(sc[1] - DECAYF * (float)(r0 - c1)) : 0.f;
        float p2 = (r1 >= c0) ? __expf(sc[2] - DECAYF * (float)(r1 - c0)) : 0.f;
        float p3 = (r1 >= c1) ? __expf(sc[3] - DECAYF * (float)(r1 - c1)) : 0.f;
        lsum0 += p0 + p1;
        lsum1 += p2 + p3;
        __nv_bfloat16 h0, l0, h1, l1;
        bsplit(p0, h0, l0); bsplit(p1, h1, l1);
        *(unsigned*)&Phi[par0 + pc] = pack2(h0, h1);
        *(unsigned*)&Plo[par0 + pc] = pack2(l0, l1);
        bsplit(p2, h0, l0); bsplit(p3, h1, l1);
        *(unsigned*)&Phi[par1 + pc] = pack2(h0, h1);
        *(unsigned*)&Plo[par1 + pc] = pack2(l0, l1);
        __syncthreads();                      // S3: P tile ready

        // PV: O += P V, bf16 3-pass
        #pragma unroll
        for (int ks2 = 0; ks2 < 2; ks2++) {
            unsigned ah[4], al[4];
            ldmx4(ah, aPhi + ks2 * 32);
            ldmx4(al, aPlo + ks2 * 32);
            unsigned vh = bVhi + (unsigned)(ks2 * 16 * KQS * 2);
            unsigned vl = bVlo + (unsigned)(ks2 * 16 * KQS * 2);
            #pragma unroll
            for (int nf = 0; nf < 16; nf++) {
                unsigned bh[2], bl[2];
                ldmx2t(bh, vh + nf * 16);
                ldmx2t(bl, vl + nf * 16);
                mma_bf16(acc[nf], ah, bh);
                mma_bf16(acc[nf], ah, bl);
                mma_bf16(acc[nf], al, bh);
            }
        }
    }

    // final l reduction: quad (cols within warp) then across the 4 warps (cg)
    lsum0 += __shfl_xor_sync(0xffffffffu, lsum0, 1);
    lsum0 += __shfl_xor_sync(0xffffffffu, lsum0, 2);
    lsum1 += __shfl_xor_sync(0xffffffffu, lsum1, 1);
    lsum1 += __shfl_xor_sync(0xffffffffu, lsum1, 2);
    __syncthreads();                          // PV reads done before redl reuse
    if (tig == 0) {
        redl[cg * 32 + rg * 16 + g4]     = lsum0;
        redl[cg * 32 + rg * 16 + g4 + 8] = lsum1;
    }
    __syncthreads();
    int row0 = rg * 16 + g4;
    float lt0 = redl[row0] + redl[32 + row0] + redl[64 + row0] + redl[96 + row0];
    float lt1 = redl[row0 + 8] + redl[32 + row0 + 8] + redl[64 + row0 + 8] + redl[96 + row0 + 8];
    float li0 = 1.f / lt0;
    float li1 = 1.f / lt1;

    size_t orow0 = (size_t)(n * LQ + q0 + row0) * (2 * DD);
    size_t orow1 = orow0 + (size_t)8 * (2 * DD);
    #pragma unroll
    for (int nf = 0; nf < 16; nf++) {
        int col = zb * DD + cg * 128 + nf * 8 + 2 * tig;
        __nv_bfloat16 h0, l0, h1, l1;
        bsplit(acc[nf][0] * li0, h0, l0);
        bsplit(acc[nf][1] * li0, h1, l1);
        *(unsigned*)&g_cat_hi[orow0 + col] = pack2(h0, h1);
        *(unsigned*)&g_cat_lo[orow0 + col] = pack2(l0, l1);
        bsplit(acc[nf][2] * li1, h0, l0);
        bsplit(acc[nf][3] * li1, h1, l1);
        *(unsigned*)&g_cat_hi[orow1 + col] = pack2(h0, h1);
        *(unsigned*)&g_cat_lo[orow1 + col] = pack2(l0, l1);
    }
}

// ---------------------------------------------------------------------------
// fusion: out = cat @ W^T + bias, bf16 3-pass legacy mma, 64x64 tiles
// (at the measured legacy HMMA floor of 512 MAC/cyc/SM)
// ---------------------------------------------------------------------------
__global__ void __launch_bounds__(256) fusion_kernel(const float* __restrict__ bias,
                                                     float* __restrict__ out) {
    __shared__ __nv_bfloat16 Ahi[64 * 72], Alo[64 * 72], Bhi[64 * 72], Blo[64 * 72];
    int bm = blockIdx.x * 64;
    int bn = blockIdx.y * 64;
    int tid = threadIdx.x;
    int w = tid >> 5, lane = tid & 31;
    int g4 = lane >> 2, tig = lane & 3, lane7 = lane & 7;
    int rg = w & 3, cg = w >> 2;
    int lrow = lane7 + ((lane >> 3) & 1) * 8;
    int lk8b = (lane >> 4) * 16;
    int bk8b = ((lane >> 3) & 1) * 16;

    unsigned ahiB = (unsigned)__cvta_generic_to_shared(Ahi) + (unsigned)((rg * 16 + lrow) * 144) + lk8b;
    unsigned aloB = (unsigned)__cvta_generic_to_shared(Alo) + (unsigned)((rg * 16 + lrow) * 144) + lk8b;
    unsigned bhiB = (unsigned)__cvta_generic_to_shared(Bhi) + (unsigned)((cg * 32 + lane7) * 144) + bk8b;
    unsigned bloB = (unsigned)__cvta_generic_to_shared(Blo) + (unsigned)((cg * 32 + lane7) * 144) + bk8b;

    float acc[4][4];
    #pragma unroll
    for (int i = 0; i < 4; i++) { acc[i][0] = acc[i][1] = acc[i][2] = acc[i][3] = 0.f; }

    for (int kc = 0; kc < 16; kc++) {
        __syncthreads();
        #pragma unroll
        for (int i0 = 0; i0 < 2; i0++) {
            int idx = tid + i0 * 256;
            int r = idx >> 3, c8 = (idx & 7) << 3;
            *(uint4*)&Ahi[r * 72 + c8] = *(const uint4*)&g_cat_hi[(size_t)(bm + r) * 1024 + kc * 64 + c8];
            *(uint4*)&Alo[r * 72 + c8] = *(const uint4*)&g_cat_lo[(size_t)(bm + r) * 1024 + kc * 64 + c8];
            *(uint4*)&Bhi[r * 72 + c8] = *(const uint4*)&g_W_hi[(size_t)(bn + r) * 1024 + kc * 64 + c8];
            *(uint4*)&Blo[r * 72 + c8] = *(const uint4*)&g_W_lo[(size_t)(bn + r) * 1024 + kc * 64 + c8];
        }
        __syncthreads();
        #pragma unroll
        for (int ks2 = 0; ks2 < 4; ks2++) {
            unsigned o = ks2 * 32;
            unsigned ah[4], al[4];
            ldmx4(ah, ahiB + o);
            ldmx4(al, aloB + o);
            #pragma unroll
            for (int nf = 0; nf < 4; nf++) {
                unsigned bh[2], bl[2];
                ldmx2(bh, bhiB + (unsigned)(nf * 1152) + o);
                ldmx2(bl, bloB + (unsigned)(nf * 1152) + o);
                mma_bf16(acc[nf], ah, bh);
                mma_bf16(acc[nf], ah, bl);
                mma_bf16(acc[nf], al, bh);
            }
        }
    }

    int orow0 = bm + rg * 16 + g4, orow1 = orow0 + 8;
    #pragma unroll
    for (int nf = 0; nf < 4; nf++) {
        int col = bn + cg * 32 + nf * 8 + 2 * tig;
        float b0v = bias[col], b1v = bias[col + 1];
        *(float2*)&out[(size_t)orow0 * 512 + col] = make_float2(acc[nf][0] + b0v, acc[nf][1] + b1v);
        *(float2*)&out[(size_t)orow1 * 512 + col] = make_float2(acc[nf][2] + b0v, acc[nf][3] + b1v);
    }
}

// ---------------------------------------------------------------------------
extern "C" void kernel_launch(void* const* d_in, const int* in_sizes, int n_in,
                              void* d_out, int out_size) {
    const float* x  = (const float*)d_in[0];
    const float* w3 = (const float*)d_in[1];
    const float* w5 = (const float*)d_in[2];
    const float* fw = (const float*)d_in[3];
    const float* fb = (const float*)d_in[4];
    float* out = (float*)d_out;

    prep_kernel<<<NB * LQ / 8, 256>>>(x, w3, w5);
    wsplit_kernel<<<(DD * 2 * DD) / 256, 256>>>(fw);

    cudaFuncSetAttribute(attn_kernel,
                         cudaFuncAttributeMaxDynamicSharedMemorySize, SMEM_ATTN);
    dim3 ga(LQ / 32, NB, 2);
    attn_kernel<<<ga, 256, SMEM_ATTN>>>();

    dim3 gf((NB * LQ) / 64, DD / 64);
    fusion_kernel<<<gf, 256>>>(fb, out);
}

// round 11
// speedup vs baseline: 6.5516x; 1.0593x over previous
#include <cuda_runtime.h>
#include <cuda_bf16.h>
#include <math.h>

#define NB 8
#define LQ 2048
#define DD 512
#define DECAYF 0.2f
#define WTILES 2     // window: current + 2 previous 32-row tiles (tail mass < 3.4e-5)
#define KQS 520
#define PS2 40

// attn smem offsets
#define OFF_QHI 0
#define OFF_QLO 33280
#define OFF_KHI 66560
#define OFF_KLO 99840
#define OFF_PHI 133120
#define OFF_PLO 135680
#define OFF_RED 138240
#define SMEM_ATTN (OFF_RED + 512)

// fusion tiling: CTA 128x64, warp 32x32, K-chunk 32, double-buffered cp.async
#define FST 40                    // smem row stride (bf16 elems) -> 80 B
#define F_AHI 0
#define F_ALO 10240
#define F_BHI 20480
#define F_BLO 25600
#define F_BUF 30720
#define SMEM_FUS (2 * F_BUF)

// Scratch (device globals: allocation-free per harness rules)
__device__ __nv_bfloat16 g_Xs_hi[NB * LQ * DD];
__device__ __nv_bfloat16 g_Xs_lo[NB * LQ * DD];
__device__ __nv_bfloat16 g_Xt_hi[NB * LQ * DD];
__device__ __nv_bfloat16 g_Xt_lo[NB * LQ * DD];
__device__ __nv_bfloat16 g_cat_hi[NB * LQ * 2 * DD];
__device__ __nv_bfloat16 g_cat_lo[NB * LQ * 2 * DD];
__device__ __nv_bfloat16 g_W_hi[DD * 2 * DD];
__device__ __nv_bfloat16 g_W_lo[DD * 2 * DD];

// ---------------------------------------------------------------------------
// mma / ldmatrix / cp.async helpers (legacy mma.sync — tcgen05 rejected by
// this toolchain's sm_103 non-'a' target)
// ---------------------------------------------------------------------------
__device__ __forceinline__ void ldmx4(unsigned* r, unsigned a) {
    asm volatile("ldmatrix.sync.aligned.m8n8.x4.shared.b16 {%0,%1,%2,%3}, [%4];"
        : "=r"(r[0]), "=r"(r[1]), "=r"(r[2]), "=r"(r[3]) : "r"(a));
}
__device__ __forceinline__ void ldmx2(unsigned* r, unsigned a) {
    asm volatile("ldmatrix.sync.aligned.m8n8.x2.shared.b16 {%0,%1}, [%2];"
        : "=r"(r[0]), "=r"(r[1]) : "r"(a));
}
__device__ __forceinline__ void ldmx2t(unsigned* r, unsigned a) {
    asm volatile("ldmatrix.sync.aligned.m8n8.x2.trans.shared.b16 {%0,%1}, [%2];"
        : "=r"(r[0]), "=r"(r[1]) : "r"(a));
}
__device__ __forceinline__ void mma_bf16(float* c, const unsigned* a, const unsigned* b) {
    asm volatile("mma.sync.aligned.m16n8k16.row.col.f32.bf16.bf16.f32 "
        "{%0,%1,%2,%3}, {%4,%5,%6,%7}, {%8,%9}, {%0,%1,%2,%3};"
        : "+f"(c[0]), "+f"(c[1]), "+f"(c[2]), "+f"(c[3])
        : "r"(a[0]), "r"(a[1]), "r"(a[2]), "r"(a[3]), "r"(b[0]), "r"(b[1]));
}
__device__ __forceinline__ void cpa16(unsigned saddr, const void* g) {
    asm volatile("cp.async.cg.shared.global [%0], [%1], 16;"
        :: "r"(saddr), "l"(g) : "memory");
}
#define CPA_COMMIT() asm volatile("cp.async.commit_group;" ::: "memory")
#define CPA_WAIT1()  asm volatile("cp.async.wait_group 1;" ::: "memory")
#define CPA_WAIT0()  asm volatile("cp.async.wait_group 0;" ::: "memory")

__device__ __forceinline__ void bsplit(float x, __nv_bfloat16& h, __nv_bfloat16& l) {
    h = __float2bfloat16(x);
    l = __float2bfloat16(x - __bfloat162float(h));
}
__device__ __forceinline__ unsigned pack2(__nv_bfloat16 a, __nv_bfloat16 b) {
    return ((unsigned)__bfloat16_as_ushort(b) << 16) | (unsigned)__bfloat16_as_ushort(a);
}
__device__ __forceinline__ float warpSum(float v) {
    #pragma unroll
    for (int o = 16; o > 0; o >>= 1) v += __shfl_xor_sync(0xffffffffu, v, o);
    return v;
}

// ---------------------------------------------------------------------------
// Warp-level routing
// ---------------------------------------------------------------------------
__device__ __forceinline__ void routing16(const float* u0, const float* u1, float* vout) {
    float b0 = 0.f, b1 = 0.f;
    #pragma unroll
    for (int it = 0; it < 3; it++) {
        float mx = fmaxf(b0, b1);
        float e0 = __expf(b0 - mx), e1 = __expf(b1 - mx);
        float inv = 1.f / (e0 + e1);
        float c0 = e0 * inv, c1 = e1 * inv;
        float loc = 0.f;
        #pragma unroll
        for (int i = 0; i < 16; i++) {
            float s = c0 * u0[i] + c1 * u1[i];
            vout[i] = s;
            loc = fmaf(s, s, loc);
        }
        float n2 = warpSum(loc);
        float nrm = sqrtf(n2);
        float scl = n2 / ((1.f + n2) * (nrm + 1e-9f));
        #pragma unroll
        for (int i = 0; i < 16; i++) vout[i] *= scl;
        if (it < 2) {
            float l0 = 0.f, l1 = 0.f;
            #pragma unroll
            for (int i = 0; i < 16; i++) {
                l0 = fmaf(u0[i], vout[i], l0);
                l1 = fmaf(u1[i], vout[i], l1);
            }
            b0 += warpSum(l0);
            b1 += warpSum(l1);
        }
    }
}

// ---------------------------------------------------------------------------
// Kernel 1: convs + routing, warp-per-row
// ---------------------------------------------------------------------------
__global__ void __launch_bounds__(256) prep_kernel(const float* __restrict__ x,
                                                   const float* __restrict__ w3,
                                                   const float* __restrict__ w5) {
    int wid = threadIdx.x >> 5, lane = threadIdx.x & 31;
    int row = blockIdx.x * 8 + wid;
    int n = row >> 11, l = row & 2047;
    const float* xb = x + (size_t)n * LQ * DD;

    float xv[16], t3[16], t5[16];
    #pragma unroll
    for (int i = 0; i < 16; i++) {
        int c = lane + 32 * i;
        float a3 = 0.f, a5 = 0.f, xx = 0.f;
        #pragma unroll
        for (int j = 0; j < 5; j++) {
            int ll = l - 4 + j;
            xx = (ll >= 0) ? __ldg(xb + (size_t)ll * DD + c) : 0.f;
            a5 = fmaf(w5[c * 5 + j], xx, a5);
            if (j >= 2) a3 = fmaf(w3[c * 3 + (j - 2)], xx, a3);
        }
        xv[i] = xx; t3[i] = a3; t5[i] = a5;
    }

    float u0[16], u1[16], v[16];
    __nv_bfloat16 h, lo;
    #pragma unroll
    for (int i = 0; i < 16; i++) { u0[i] = xv[i] - t3[i]; u1[i] = xv[i] - t5[i]; }
    routing16(u0, u1, v);
    #pragma unroll
    for (int i = 0; i < 16; i++) {
        int c = lane + 32 * i;
        bsplit(v[i], h, lo);
        g_Xs_hi[(size_t)row * DD + c] = h;
        g_Xs_lo[(size_t)row * DD + c] = lo;
    }
    routing16(t3, t5, v);
    #pragma unroll
    for (int i = 0; i < 16; i++) {
        int c = lane + 32 * i;
        bsplit(v[i], h, lo);
        g_Xt_hi[(size_t)row * DD + c] = h;
        g_Xt_lo[(size_t)row * DD + c] = lo;
    }
}

__global__ void wsplit_kernel(const float* __restrict__ W) {
    int i = blockIdx.x * 256 + threadIdx.x;
    __nv_bfloat16 h, l;
    bsplit(W[i], h, l);
    g_W_hi[i] = h;
    g_W_lo[i] = l;
}

// ---------------------------------------------------------------------------
// attention: windowed flash, bf16 3-pass, fixed-shift softmax (unchanged R9)
// ---------------------------------------------------------------------------
__global__ void __launch_bounds__(256, 1) attn_kernel() {
    extern __shared__ char smraw[];
    __nv_bfloat16* Qhi = (__nv_bfloat16*)(smraw + OFF_QHI);
    __nv_bfloat16* Qlo = (__nv_bfloat16*)(smraw + OFF_QLO);
    __nv_bfloat16* Khi = (__nv_bfloat16*)(smraw + OFF_KHI);
    __nv_bfloat16* Klo = (__nv_bfloat16*)(smraw + OFF_KLO);
    __nv_bfloat16* Phi = (__nv_bfloat16*)(smraw + OFF_PHI);
    __nv_bfloat16* Plo = (__nv_bfloat16*)(smraw + OFF_PLO);
    float* redl = (float*)(smraw + OFF_RED);

    int zb = blockIdx.z;
    const __nv_bfloat16* Xhi = (zb ? g_Xt_hi : g_Xs_hi) + (size_t)blockIdx.y * LQ * DD;
    const __nv_bfloat16* Xlo = (zb ? g_Xt_lo : g_Xs_lo) + (size_t)blockIdx.y * LQ * DD;
    int n = blockIdx.y;
    int qb = blockIdx.x;
    int tid = threadIdx.x;
    int w = tid >> 5, lane = tid & 31;
    int g4 = lane >> 2, tig = lane & 3, lane7 = lane & 7;
    int q0 = qb * 32;
    int rg = w & 1, cg = w >> 1;

    unsigned sb = (unsigned)__cvta_generic_to_shared(smraw);
    int lrow = lane7 + ((lane >> 3) & 1) * 8;
    int lk8b = (lane >> 4) * 16;
    int bk8b = ((lane >> 3) & 1) * 16;

    unsigned aQhi = sb + OFF_QHI + (unsigned)((rg * 16 + lrow) * KQS * 2) + lk8b;
    unsigned aQlo = sb + OFF_QLO + (unsigned)((rg * 16 + lrow) * KQS * 2) + lk8b;
    unsigned bKhi = sb + OFF_KHI + (unsigned)((cg * 8 + lane7) * KQS * 2) + bk8b;
    unsigned bKlo = sb + OFF_KLO + (unsigned)((cg * 8 + lane7) * KQS * 2) + bk8b;
    unsigned aPhi = sb + OFF_PHI + (unsigned)((rg * 16 + lrow) * PS2 * 2) + lk8b;
    unsigned aPlo = sb + OFF_PLO + (unsigned)((rg * 16 + lrow) * PS2 * 2) + lk8b;
    unsigned bVhi = sb + OFF_KHI + (unsigned)(lrow * KQS * 2) + (unsigned)(cg * 256);
    unsigned bVlo = sb + OFF_KLO + (unsigned)(lrow * KQS * 2) + (unsigned)(cg * 256);

    #pragma unroll
    for (int i0 = 0; i0 < 8; i0++) {
        int i = tid + i0 * 256;
        int r = i >> 6, c8 = (i & 63) << 3;
        *(uint4*)&Qhi[r * KQS + c8] = *(const uint4*)&Xhi[(size_t)(q0 + r) * DD + c8];
        *(uint4*)&Qlo[r * KQS + c8] = *(const uint4*)&Xlo[(size_t)(q0 + r) * DD + c8];
    }

    float acc[16][4];
    #pragma unroll
    for (int i = 0; i < 16; i++) { acc[i][0] = acc[i][1] = acc[i][2] = acc[i][3] = 0.f; }
    float lsum0 = 0.f, lsum1 = 0.f;

    int par0 = (rg * 16 + g4) * PS2;
    int par1 = (rg * 16 + g4 + 8) * PS2;
    int pc = cg * 8 + 2 * tig;

    int kb0 = (qb >= WTILES) ? qb - WTILES : 0;
    for (int kb = kb0; kb <= qb; kb++) {
        __syncthreads();
        #pragma unroll
        for (int i0 = 0; i0 < 8; i0++) {
            int i = tid + i0 * 256;
            int r = i >> 6, c8 = (i & 63) << 3;
            *(uint4*)&Khi[r * KQS + c8] = *(const uint4*)&Xhi[(size_t)(kb * 32 + r) * DD + c8];
            *(uint4*)&Klo[r * KQS + c8] = *(const uint4*)&Xlo[(size_t)(kb * 32 + r) * DD + c8];
        }
        __syncthreads();

        float sc[4] = {0.f, 0.f, 0.f, 0.f};
        #pragma unroll 8
        for (int ks2 = 0; ks2 < 32; ks2++) {
            unsigned o = ks2 * 32;
            unsigned ah[4], al[4], bh[2], bl[2];
            ldmx4(ah, aQhi + o);
            ldmx4(al, aQlo + o);
            ldmx2(bh, bKhi + o);
            ldmx2(bl, bKlo + o);
            mma_bf16(sc, ah, bh);
            mma_bf16(sc, ah, bl);
            mma_bf16(sc, al, bh);
        }
        int r0 = q0 + rg * 16 + g4, r1 = r0 + 8;
        int c0 = kb * 32 + cg * 8 + 2 * tig, c1 = c0 + 1;

        float p0 = (r0 >= c0) ? __expf(sc[0] - DECAYF * (float)(r0 - c0)) : 0.f;
        float p1 = (r0 >= c1) ? __expf(sc[1] - DECAYF * (float)(r0 - c1)) : 0.f;
        float p2 = (r1 >= c0) ? __expf(sc[2] - DECAYF * (float)(r1 - c0)) : 0.f;
        float p3 = (r1 >= c1) ? __expf(sc[3] - DECAYF * (float)(r1 - c1)) : 0.f;
        lsum0 += p0 + p1;
        lsum1 += p2 + p3;
        __nv_bfloat16 h0, l0, h1, l1;
        bsplit(p0, h0, l0); bsplit(p1, h1, l1);
        *(unsigned*)&Phi[par0 + pc] = pack2(h0, h1);
        *(unsigned*)&Plo[par0 + pc] = pack2(l0, l1);
        bsplit(p2, h0, l0); bsplit(p3, h1, l1);
        *(unsigned*)&Phi[par1 + pc] = pack2(h0, h1);
        *(unsigned*)&Plo[par1 + pc] = pack2(l0, l1);
        __syncthreads();

        #pragma unroll
        for (int ks2 = 0; ks2 < 2; ks2++) {
            unsigned ah[4], al[4];
            ldmx4(ah, aPhi + ks2 * 32);
            ldmx4(al, aPlo + ks2 * 32);
            unsigned vh = bVhi + (unsigned)(ks2 * 16 * KQS * 2);
            unsigned vl = bVlo + (unsigned)(ks2 * 16 * KQS * 2);
            #pragma unroll
            for (int nf = 0; nf < 16; nf++) {
                unsigned bh[2], bl[2];
                ldmx2t(bh, vh + nf * 16);
                ldmx2t(bl, vl + nf * 16);
                mma_bf16(acc[nf], ah, bh);
                mma_bf16(acc[nf], ah, bl);
                mma_bf16(acc[nf], al, bh);
            }
        }
    }

    lsum0 += __shfl_xor_sync(0xffffffffu, lsum0, 1);
    lsum0 += __shfl_xor_sync(0xffffffffu, lsum0, 2);
    lsum1 += __shfl_xor_sync(0xffffffffu, lsum1, 1);
    lsum1 += __shfl_xor_sync(0xffffffffu, lsum1, 2);
    __syncthreads();
    if (tig == 0) {
        redl[cg * 32 + rg * 16 + g4]     = lsum0;
        redl[cg * 32 + rg * 16 + g4 + 8] = lsum1;
    }
    __syncthreads();
    int row0 = rg * 16 + g4;
    float lt0 = redl[row0] + redl[32 + row0] + redl[64 + row0] + redl[96 + row0];
    float lt1 = redl[row0 + 8] + redl[32 + row0 + 8] + redl[64 + row0 + 8] + redl[96 + row0 + 8];
    float li0 = 1.f / lt0;
    float li1 = 1.f / lt1;

    size_t orow0 = (size_t)(n * LQ + q0 + row0) * (2 * DD);
    size_t orow1 = orow0 + (size_t)8 * (2 * DD);
    #pragma unroll
    for (int nf = 0; nf < 16; nf++) {
        int col = zb * DD + cg * 128 + nf * 8 + 2 * tig;
        __nv_bfloat16 h0, l0, h1, l1;
        bsplit(acc[nf][0] * li0, h0, l0);
        bsplit(acc[nf][1] * li0, h1, l1);
        *(unsigned*)&g_cat_hi[orow0 + col] = pack2(h0, h1);
        *(unsigned*)&g_cat_lo[orow0 + col] = pack2(l0, l1);
        bsplit(acc[nf][2] * li1, h0, l0);
        bsplit(acc[nf][3] * li1, h1, l1);
        *(unsigned*)&g_cat_hi[orow1 + col] = pack2(h0, h1);
        *(unsigned*)&g_cat_lo[orow1 + col] = pack2(l0, l1);
    }
}

// ---------------------------------------------------------------------------
// fusion: out[16384,512] = cat @ W^T + bias, bf16 3-pass
// CTA 128x64, warp 32x32, K-chunk 32, cp.async double-buffered
// ---------------------------------------------------------------------------
__device__ __forceinline__ void fus_fill(unsigned sbuf, int kc, int bm, int bn, int tid) {
    // A: 128 rows x 32 k-elems, hi+lo (2 x 16B per thread per plane)
    #pragma unroll
    for (int i = 0; i < 2; i++) {
        int idx = tid + i * 256;
        int r = idx >> 2, c8 = (idx & 3) << 3;
        unsigned off = (unsigned)(r * (FST * 2) + c8 * 2);
        size_t src = (size_t)(bm + r) * 1024 + kc * 32 + c8;
        cpa16(sbuf + F_AHI + off, &g_cat_hi[src]);
        cpa16(sbuf + F_ALO + off, &g_cat_lo[src]);
    }
    // B: 64 rows x 32 k-elems, hi+lo (1 x 16B per thread per plane)
    {
        int r = tid >> 2, c8 = (tid & 3) << 3;
        unsigned off = (unsigned)(r * (FST * 2) + c8 * 2);
        size_t src = (size_t)(bn + r) * 1024 + kc * 32 + c8;
        cpa16(sbuf + F_BHI + off, &g_W_hi[src]);
        cpa16(sbuf + F_BLO + off, &g_W_lo[src]);
    }
    CPA_COMMIT();
}

__global__ void __launch_bounds__(256, 3) fusion_kernel(const float* __restrict__ bias,
                                                        float* __restrict__ out) {
    extern __shared__ char fsm[];
    unsigned sb = (unsigned)__cvta_generic_to_shared(fsm);
    int tid = threadIdx.x;
    int w = tid >> 5, lane = tid & 31;
    int g4 = lane >> 2, tig = lane & 3, lane7 = lane & 7;
    int rg = w & 3, cg = w >> 2;            // warp tile: rows rg*32..+32, cols cg*32..+32
    int bm = blockIdx.x * 128;
    int bn = blockIdx.y * 64;
    int lrow = lane7 + ((lane >> 3) & 1) * 8;
    int lk8b = (lane >> 4) * 16;
    int bk8b = ((lane >> 3) & 1) * 16;

    float acc[2][4][4];
    #pragma unroll
    for (int t = 0; t < 2; t++)
        #pragma unroll
        for (int nf = 0; nf < 4; nf++) {
            acc[t][nf][0] = 0.f; acc[t][nf][1] = 0.f;
            acc[t][nf][2] = 0.f; acc[t][nf][3] = 0.f;
        }

    fus_fill(sb, 0, bm, bn, tid);
    fus_fill(sb + F_BUF, 1, bm, bn, tid);

    // per-warp base addresses (byte offsets within a buffer)
    unsigned aoff0 = (unsigned)((rg * 32 + lrow) * (FST * 2)) + lk8b;        // m16 tile 0
    unsigned aoff1 = (unsigned)((rg * 32 + 16 + lrow) * (FST * 2)) + lk8b;   // m16 tile 1
    unsigned boffs[4];
    #pragma unroll
    for (int nf = 0; nf < 4; nf++)
        boffs[nf] = (unsigned)((cg * 32 + nf * 8 + lane7) * (FST * 2)) + bk8b;

    for (int c = 0; c < 32; c++) {
        unsigned base = sb + (unsigned)(c & 1) * F_BUF;
        CPA_WAIT1();
        __syncthreads();               // chunk c data visible to all threads

        #pragma unroll
        for (int ks = 0; ks < 2; ks++) {
            unsigned ko = (unsigned)(ks * 32);
            unsigned ah0[4], ah1[4], al0[4], al1[4];
            ldmx4(ah0, base + F_AHI + aoff0 + ko);
            ldmx4(ah1, base + F_AHI + aoff1 + ko);
            ldmx4(al0, base + F_ALO + aoff0 + ko);
            ldmx4(al1, base + F_ALO + aoff1 + ko);
            unsigned bh[4][2], bl[4][2];
            #pragma unroll
            for (int nf = 0; nf < 4; nf++) {
                ldmx2(bh[nf], base + F_BHI + boffs[nf] + ko);
                ldmx2(bl[nf], base + F_BLO + boffs[nf] + ko);
            }
            #pragma unroll
            for (int nf = 0; nf < 4; nf++) {
                mma_bf16(acc[0][nf], ah0, bh[nf]);
                mma_bf16(acc[1][nf], ah1, bh[nf]);
                mma_bf16(acc[0][nf], ah0, bl[nf]);
                mma_bf16(acc[1][nf], ah1, bl[nf]);
                mma_bf16(acc[0][nf], al0, bh[nf]);
                mma_bf16(acc[1][nf], al1, bh[nf]);
            }
        }
        __syncthreads();               // all warps done reading buffer (c&1)
        if (c + 2 < 32) fus_fill(base, c + 2, bm, bn, tid);
    }

    #pragma unroll
    for (int t = 0; t < 2; t++) {
        int orow0 = bm + rg * 32 + t * 16 + g4;
        int orow1 = orow0 + 8;
        #pragma unroll
        for (int nf = 0; nf < 4; nf++) {
            int col = bn + cg * 32 + nf * 8 + 2 * tig;
            float b0v = bias[col], b1v = bias[col + 1];
            *(float2*)&out[(size_t)orow0 * 512 + col] =
                make_float2(acc[t][nf][0] + b0v, acc[t][nf][1] + b1v);
            *(float2*)&out[(size_t)orow1 * 512 + col] =
                make_float2(acc[t][nf][2] + b0v, acc[t][nf][3] + b1v);
        }
    }
}

// ---------------------------------------------------------------------------
extern "C" void kernel_launch(void* const* d_in, const int* in_sizes, int n_in,
                              void* d_out, int out_size) {
    const float* x  = (const float*)d_in[0];
    const float* w3 = (const float*)d_in[1];
    const float* w5 = (const float*)d_in[2];
    const float* fw = (const float*)d_in[3];
    const float* fb = (const float*)d_in[4];
    float* out = (float*)d_out;

    prep_kernel<<<NB * LQ / 8, 256>>>(x, w3, w5);
    wsplit_kernel<<<(DD * 2 * DD) / 256, 256>>>(fw);

    cudaFuncSetAttribute(attn_kernel,
                         cudaFuncAttributeMaxDynamicSharedMemorySize, SMEM_ATTN);
    dim3 ga(LQ / 32, NB, 2);
    attn_kernel<<<ga, 256, SMEM_ATTN>>>();

    cudaFuncSetAttribute(fusion_kernel,
                         cudaFuncAttributeMaxDynamicSharedMemorySize, SMEM_FUS);
    dim3 gf((NB * LQ) / 128, DD / 64);   // (128, 8) = 1024 CTAs
    fusion_kernel<<<gf, 256, SMEM_FUS>>>(fb, out);
}

// round 12
// speedup vs baseline: 12.7477x; 1.9457x over previous
#include <cuda_runtime.h>
#include <cuda_fp16.h>
#include <math.h>

#define NB 8
#define LQ 2048
#define DD 512
#define DECAYF 0.2f
#define WTILES 2     // window: current + 2 previous 32-row tiles (tail mass < 3.4e-5)
#define KQS 520      // Q/K smem stride (fp16 elems) -> 1040 B
#define PS2 40       // P smem stride (fp16 elems) -> 80 B

// attn smem byte offsets (fp16 single-plane)
#define OFF_Q 0
#define OFF_K 33280
#define OFF_P 66560
#define OFF_RED 69120
#define SMEM_ATTN (OFF_RED + 512)

// fusion tiling: CTA 128x64, warp 32x32, K-chunk 32, double-buffered cp.async
#define FST 40                    // smem row stride (fp16 elems) -> 80 B
#define F_A 0
#define F_B 10240
#define F_BUF 15360
#define SMEM_FUS (2 * F_BUF)

// Scratch (device globals: allocation-free per harness rules)
__device__ __half g_Xs[NB * LQ * DD];
__device__ __half g_Xt[NB * LQ * DD];
__device__ __half g_cat[NB * LQ * 2 * DD];
__device__ __half g_W[DD * 2 * DD];

// ---------------------------------------------------------------------------
// mma / ldmatrix / cp.async helpers (legacy mma.sync — tcgen05 rejected by
// this toolchain's sm_103 non-'a' target)
// ---------------------------------------------------------------------------
__device__ __forceinline__ void ldmx4(unsigned* r, unsigned a) {
    asm volatile("ldmatrix.sync.aligned.m8n8.x4.shared.b16 {%0,%1,%2,%3}, [%4];"
        : "=r"(r[0]), "=r"(r[1]), "=r"(r[2]), "=r"(r[3]) : "r"(a));
}
__device__ __forceinline__ void ldmx2(unsigned* r, unsigned a) {
    asm volatile("ldmatrix.sync.aligned.m8n8.x2.shared.b16 {%0,%1}, [%2];"
        : "=r"(r[0]), "=r"(r[1]) : "r"(a));
}
__device__ __forceinline__ void ldmx2t(unsigned* r, unsigned a) {
    asm volatile("ldmatrix.sync.aligned.m8n8.x2.trans.shared.b16 {%0,%1}, [%2];"
        : "=r"(r[0]), "=r"(r[1]) : "r"(a));
}
__device__ __forceinline__ void mma_f16(float* c, const unsigned* a, const unsigned* b) {
    asm volatile("mma.sync.aligned.m16n8k16.row.col.f32.f16.f16.f32 "
        "{%0,%1,%2,%3}, {%4,%5,%6,%7}, {%8,%9}, {%0,%1,%2,%3};"
        : "+f"(c[0]), "+f"(c[1]), "+f"(c[2]), "+f"(c[3])
        : "r"(a[0]), "r"(a[1]), "r"(a[2]), "r"(a[3]), "r"(b[0]), "r"(b[1]));
}
__device__ __forceinline__ void cpa16(unsigned saddr, const void* g) {
    asm volatile("cp.async.cg.shared.global [%0], [%1], 16;"
        :: "r"(saddr), "l"(g) : "memory");
}
#define CPA_COMMIT() asm volatile("cp.async.commit_group;" ::: "memory")
#define CPA_WAIT1()  asm volatile("cp.async.wait_group 1;" ::: "memory")

__device__ __forceinline__ unsigned packh2(float a, float b) {
    __half2 h = __floats2half2_rn(a, b);
    return *(unsigned*)&h;
}
__device__ __forceinline__ float warpSum(float v) {
    #pragma unroll
    for (int o = 16; o > 0; o >>= 1) v += __shfl_xor_sync(0xffffffffu, v, o);
    return v;
}

// ---------------------------------------------------------------------------
// Warp-level routing
// ---------------------------------------------------------------------------
__device__ __forceinline__ void routing16(const float* u0, const float* u1, float* vout) {
    float b0 = 0.f, b1 = 0.f;
    #pragma unroll
    for (int it = 0; it < 3; it++) {
        float mx = fmaxf(b0, b1);
        float e0 = __expf(b0 - mx), e1 = __expf(b1 - mx);
        float inv = 1.f / (e0 + e1);
        float c0 = e0 * inv, c1 = e1 * inv;
        float loc = 0.f;
        #pragma unroll
        for (int i = 0; i < 16; i++) {
            float s = c0 * u0[i] + c1 * u1[i];
            vout[i] = s;
            loc = fmaf(s, s, loc);
        }
        float n2 = warpSum(loc);
        float nrm = sqrtf(n2);
        float scl = n2 / ((1.f + n2) * (nrm + 1e-9f));
        #pragma unroll
        for (int i = 0; i < 16; i++) vout[i] *= scl;
        if (it < 2) {
            float l0 = 0.f, l1 = 0.f;
            #pragma unroll
            for (int i = 0; i < 16; i++) {
                l0 = fmaf(u0[i], vout[i], l0);
                l1 = fmaf(u1[i], vout[i], l1);
            }
            b0 += warpSum(l0);
            b1 += warpSum(l1);
        }
    }
}

// ---------------------------------------------------------------------------
// Kernel 1: convs + routing, warp-per-row, writes fp16 planes
// ---------------------------------------------------------------------------
__global__ void __launch_bounds__(256) prep_kernel(const float* __restrict__ x,
                                                   const float* __restrict__ w3,
                                                   const float* __restrict__ w5) {
    int wid = threadIdx.x >> 5, lane = threadIdx.x & 31;
    int row = blockIdx.x * 8 + wid;
    int n = row >> 11, l = row & 2047;
    const float* xb = x + (size_t)n * LQ * DD;

    float xv[16], t3[16], t5[16];
    #pragma unroll
    for (int i = 0; i < 16; i++) {
        int c = lane + 32 * i;
        float a3 = 0.f, a5 = 0.f, xx = 0.f;
        #pragma unroll
        for (int j = 0; j < 5; j++) {
            int ll = l - 4 + j;
            xx = (ll >= 0) ? __ldg(xb + (size_t)ll * DD + c) : 0.f;
            a5 = fmaf(w5[c * 5 + j], xx, a5);
            if (j >= 2) a3 = fmaf(w3[c * 3 + (j - 2)], xx, a3);
        }
        xv[i] = xx; t3[i] = a3; t5[i] = a5;
    }

    float u0[16], u1[16], v[16];
    #pragma unroll
    for (int i = 0; i < 16; i++) { u0[i] = xv[i] - t3[i]; u1[i] = xv[i] - t5[i]; }
    routing16(u0, u1, v);
    #pragma unroll
    for (int i = 0; i < 16; i++)
        g_Xs[(size_t)row * DD + lane + 32 * i] = __float2half(v[i]);
    routing16(t3, t5, v);
    #pragma unroll
    for (int i = 0; i < 16; i++)
        g_Xt[(size_t)row * DD + lane + 32 * i] = __float2half(v[i]);
}

__global__ void wsplit_kernel(const float* __restrict__ W) {
    int i = blockIdx.x * 256 + threadIdx.x;
    g_W[i] = __float2half(W[i]);
}

// ---------------------------------------------------------------------------
// attention: windowed flash, fp16 single-pass, fixed-shift softmax
// grid=(64, 8, 2), 256 threads, 2 CTAs/SM
// ---------------------------------------------------------------------------
__global__ void __launch_bounds__(256, 2) attn_kernel() {
    extern __shared__ char smraw[];
    __half* Qs = (__half*)(smraw + OFF_Q);
    __half* Ks = (__half*)(smraw + OFF_K);
    __half* Ps = (__half*)(smraw + OFF_P);
    float* redl = (float*)(smraw + OFF_RED);

    int zb = blockIdx.z;
    const __half* X = (zb ? g_Xt : g_Xs) + (size_t)blockIdx.y * LQ * DD;
    int n = blockIdx.y;
    int qb = blockIdx.x;
    int tid = threadIdx.x;
    int w = tid >> 5, lane = tid & 31;
    int g4 = lane >> 2, tig = lane & 3, lane7 = lane & 7;
    int q0 = qb * 32;
    int rg = w & 1, cg = w >> 1;

    unsigned sb = (unsigned)__cvta_generic_to_shared(smraw);
    int lrow = lane7 + ((lane >> 3) & 1) * 8;
    int lk8b = (lane >> 4) * 16;
    int bk8b = ((lane >> 3) & 1) * 16;

    unsigned aQ = sb + OFF_Q + (unsigned)((rg * 16 + lrow) * KQS * 2) + lk8b;
    unsigned bK = sb + OFF_K + (unsigned)((cg * 8 + lane7) * KQS * 2) + bk8b;
    unsigned aP = sb + OFF_P + (unsigned)((rg * 16 + lrow) * PS2 * 2) + lk8b;
    unsigned bV = sb + OFF_K + (unsigned)(lrow * KQS * 2) + (unsigned)(cg * 256);

    // load Q tile (32 x 512 fp16)
    #pragma unroll
    for (int i0 = 0; i0 < 8; i0++) {
        int i = tid + i0 * 256;
        int r = i >> 6, c8 = (i & 63) << 3;
        *(uint4*)&Qs[r * KQS + c8] = *(const uint4*)&X[(size_t)(q0 + r) * DD + c8];
    }

    float acc[16][4];
    #pragma unroll
    for (int i = 0; i < 16; i++) { acc[i][0] = acc[i][1] = acc[i][2] = acc[i][3] = 0.f; }
    float lsum0 = 0.f, lsum1 = 0.f;

    int par0 = (rg * 16 + g4) * PS2;
    int par1 = (rg * 16 + g4 + 8) * PS2;
    int pc = cg * 8 + 2 * tig;

    int kb0 = (qb >= WTILES) ? qb - WTILES : 0;
    for (int kb = kb0; kb <= qb; kb++) {
        __syncthreads();                      // prev iter's PV reads done
        #pragma unroll
        for (int i0 = 0; i0 < 8; i0++) {
            int i = tid + i0 * 256;
            int r = i >> 6, c8 = (i & 63) << 3;
            *(uint4*)&Ks[r * KQS + c8] = *(const uint4*)&X[(size_t)(kb * 32 + r) * DD + c8];
        }
        __syncthreads();                      // K tile ready

        // scores: S = Q K^T, single-pass fp16
        float sc[4] = {0.f, 0.f, 0.f, 0.f};
        #pragma unroll 8
        for (int ks2 = 0; ks2 < 32; ks2++) {
            unsigned o = ks2 * 32;
            unsigned ah[4], bh[2];
            ldmx4(ah, aQ + o);
            ldmx2(bh, bK + o);
            mma_f16(sc, ah, bh);
        }
        int r0 = q0 + rg * 16 + g4, r1 = r0 + 8;
        int c0 = kb * 32 + cg * 8 + 2 * tig, c1 = c0 + 1;

        float p0 = (r0 >= c0) ? __expf(sc[0] - DECAYF * (float)(r0 - c0)) : 0.f;
        float p1 = (r0 >= c1) ? __expf(sc[1] - DECAYF * (float)(r0 - c1)) : 0.f;
        float p2 = (r1 >= c0) ? __expf(sc[2] - DECAYF * (float)(r1 - c0)) : 0.f;
        float p3 = (r1 >= c1) ? __expf(sc[3] - DECAYF * (float)(r1 - c1)) : 0.f;
        lsum0 += p0 + p1;
        lsum1 += p2 + p3;
        *(unsigned*)&Ps[par0 + pc] = packh2(p0, p1);
        *(unsigned*)&Ps[par1 + pc] = packh2(p2, p3);
        __syncthreads();                      // P tile ready

        // PV: O += P V, single-pass fp16
        #pragma unroll
        for (int ks2 = 0; ks2 < 2; ks2++) {
            unsigned ah[4];
            ldmx4(ah, aP + ks2 * 32);
            unsigned vh = bV + (unsigned)(ks2 * 16 * KQS * 2);
            #pragma unroll
            for (int nf = 0; nf < 16; nf++) {
                unsigned bh[2];
                ldmx2t(bh, vh + nf * 16);
                mma_f16(acc[nf], ah, bh);
            }
        }
    }

    lsum0 += __shfl_xor_sync(0xffffffffu, lsum0, 1);
    lsum0 += __shfl_xor_sync(0xffffffffu, lsum0, 2);
    lsum1 += __shfl_xor_sync(0xffffffffu, lsum1, 1);
    lsum1 += __shfl_xor_sync(0xffffffffu, lsum1, 2);
    __syncthreads();
    if (tig == 0) {
        redl[cg * 32 + rg * 16 + g4]     = lsum0;
        redl[cg * 32 + rg * 16 + g4 + 8] = lsum1;
    }
    __syncthreads();
    int row0 = rg * 16 + g4;
    float lt0 = redl[row0] + redl[32 + row0] + redl[64 + row0] + redl[96 + row0];
    float lt1 = redl[row0 + 8] + redl[32 + row0 + 8] + redl[64 + row0 + 8] + redl[96 + row0 + 8];
    float li0 = 1.f / lt0;
    float li1 = 1.f / lt1;

    size_t orow0 = (size_t)(n * LQ + q0 + row0) * (2 * DD);
    size_t orow1 = orow0 + (size_t)8 * (2 * DD);
    #pragma unroll
    for (int nf = 0; nf < 16; nf++) {
        int col = zb * DD + cg * 128 + nf * 8 + 2 * tig;
        *(unsigned*)&g_cat[orow0 + col] = packh2(acc[nf][0] * li0, acc[nf][1] * li0);
        *(unsigned*)&g_cat[orow1 + col] = packh2(acc[nf][2] * li1, acc[nf][3] * li1);
    }
}

// ---------------------------------------------------------------------------
// fusion: out[16384,512] = cat @ W^T + bias, fp16 single-pass
// CTA 128x64, warp 32x32, K-chunk 32, cp.async double-buffered
// ---------------------------------------------------------------------------
__device__ __forceinline__ void fus_fill(unsigned sbuf, int kc, int bm, int bn, int tid) {
    // A: 128 rows x 32 k-elems fp16 (2 x 16B per thread)
    #pragma unroll
    for (int i = 0; i < 2; i++) {
        int idx = tid + i * 256;
        int r = idx >> 2, c8 = (idx & 3) << 3;
        unsigned off = (unsigned)(r * (FST * 2) + c8 * 2);
        cpa16(sbuf + F_A + off, &g_cat[(size_t)(bm + r) * 1024 + kc * 32 + c8]);
    }
    // B: 64 rows x 32 k-elems fp16 (1 x 16B per thread)
    {
        int r = tid >> 2, c8 = (tid & 3) << 3;
        unsigned off = (unsigned)(r * (FST * 2) + c8 * 2);
        cpa16(sbuf + F_B + off, &g_W[(size_t)(bn + r) * 1024 + kc * 32 + c8]);
    }
    CPA_COMMIT();
}

__global__ void __launch_bounds__(256, 3) fusion_kernel(const float* __restrict__ bias,
                                                        float* __restrict__ out) {
    extern __shared__ char fsm[];
    unsigned sb = (unsigned)__cvta_generic_to_shared(fsm);
    int tid = threadIdx.x;
    int w = tid >> 5, lane = tid & 31;
    int g4 = lane >> 2, tig = lane & 3, lane7 = lane & 7;
    int rg = w & 3, cg = w >> 2;
    int bm = blockIdx.x * 128;
    int bn = blockIdx.y * 64;
    int lrow = lane7 + ((lane >> 3) & 1) * 8;
    int lk8b = (lane >> 4) * 16;
    int bk8b = ((lane >> 3) & 1) * 16;

    float acc[2][4][4];
    #pragma unroll
    for (int t = 0; t < 2; t++)
        #pragma unroll
        for (int nf = 0; nf < 4; nf++) {
            acc[t][nf][0] = 0.f; acc[t][nf][1] = 0.f;
            acc[t][nf][2] = 0.f; acc[t][nf][3] = 0.f;
        }

    fus_fill(sb, 0, bm, bn, tid);
    fus_fill(sb + F_BUF, 1, bm, bn, tid);

    unsigned aoff0 = (unsigned)((rg * 32 + lrow) * (FST * 2)) + lk8b;
    unsigned aoff1 = (unsigned)((rg * 32 + 16 + lrow) * (FST * 2)) + lk8b;
    unsigned boffs[4];
    #pragma unroll
    for (int nf = 0; nf < 4; nf++)
        boffs[nf] = (unsigned)((cg * 32 + nf * 8 + lane7) * (FST * 2)) + bk8b;

    for (int c = 0; c < 32; c++) {
        unsigned base = sb + (unsigned)(c & 1) * F_BUF;
        CPA_WAIT1();
        __syncthreads();

        #pragma unroll
        for (int ks = 0; ks < 2; ks++) {
            unsigned ko = (unsigned)(ks * 32);
            unsigned ah0[4], ah1[4];
            ldmx4(ah0, base + F_A + aoff0 + ko);
            ldmx4(ah1, base + F_A + aoff1 + ko);
            unsigned bh[4][2];
            #pragma unroll
            for (int nf = 0; nf < 4; nf++)
                ldmx2(bh[nf], base + F_B + boffs[nf] + ko);
            #pragma unroll
            for (int nf = 0; nf < 4; nf++) {
                mma_f16(acc[0][nf], ah0, bh[nf]);
                mma_f16(acc[1][nf], ah1, bh[nf]);
            }
        }
        __syncthreads();
        if (c + 2 < 32) fus_fill(base, c + 2, bm, bn, tid);
    }

    #pragma unroll
    for (int t = 0; t < 2; t++) {
        int orow0 = bm + rg * 32 + t * 16 + g4;
        int orow1 = orow0 + 8;
        #pragma unroll
        for (int nf = 0; nf < 4; nf++) {
            int col = bn + cg * 32 + nf * 8 + 2 * tig;
            float b0v = bias[col], b1v = bias[col + 1];
            *(float2*)&out[(size_t)orow0 * 512 + col] =
                make_float2(acc[t][nf][0] + b0v, acc[t][nf][1] + b1v);
            *(float2*)&out[(size_t)orow1 * 512 + col] =
                make_float2(acc[t][nf][2] + b0v, acc[t][nf][3] + b1v);
        }
    }
}

// ---------------------------------------------------------------------------
extern "C" void kernel_launch(void* const* d_in, const int* in_sizes, int n_in,
                              void* d_out, int out_size) {
    const float* x  = (const float*)d_in[0];
    const float* w3 = (const float*)d_in[1];
    const float* w5 = (const float*)d_in[2];
    const float* fw = (const float*)d_in[3];
    const float* fb = (const float*)d_in[4];
    float* out = (float*)d_out;

    prep_kernel<<<NB * LQ / 8, 256>>>(x, w3, w5);
    wsplit_kernel<<<(DD * 2 * DD) / 256, 256>>>(fw);

    cudaFuncSetAttribute(attn_kernel,
                         cudaFuncAttributeMaxDynamicSharedMemorySize, SMEM_ATTN);
    dim3 ga(LQ / 32, NB, 2);
    attn_kernel<<<ga, 256, SMEM_ATTN>>>();

    cudaFuncSetAttribute(fusion_kernel,
                         cudaFuncAttributeMaxDynamicSharedMemorySize, SMEM_FUS);
    dim3 gf((NB * LQ) / 128, DD / 64);
    fusion_kernel<<<gf, 256, SMEM_FUS>>>(fb, out);
}

// round 13
// speedup vs baseline: 14.1817x; 1.1125x over previous
#include <cuda_runtime.h>
#include <cuda_fp16.h>
#include <math.h>

#define NB 8
#define LQ 2048
#define DD 512
#define DECAYF 0.2f
#define WTILES 2     // window: current + 2 previous 32-row tiles (tail mass < 3.4e-5)
#define KQS 520      // Q/K smem stride (fp16 elems) -> 1040 B
#define PS2 40       // P smem stride (fp16 elems) -> 80 B
#define KSZ 33280    // one K buffer (32 * KQS * 2)

// attn smem byte offsets (fp16, double-buffered K)
#define OFF_Q  0
#define OFF_K0 33280
#define OFF_K1 66560
#define OFF_P  99840
#define OFF_RED 102400
#define SMEM_ATTN (OFF_RED + 512)

// fusion tiling: CTA 128x64, warp 32x32, K-chunk 64, double-buffered cp.async
#define FROWB 144                 // smem row bytes (72 fp16): conflict-free, 16B-aligned
#define F_A 0
#define F_B 18432                 // 128 * 144
#define F_BUF 27648               // + 64 * 144
#define SMEM_FUS (2 * F_BUF)
#define FNCH 16                   // 1024 / 64

// Scratch (device globals: allocation-free per harness rules)
__device__ __half g_Xs[NB * LQ * DD];
__device__ __half g_Xt[NB * LQ * DD];
__device__ __half g_cat[NB * LQ * 2 * DD];
__device__ __half g_W[DD * 2 * DD];

// ---------------------------------------------------------------------------
// mma / ldmatrix / cp.async helpers (legacy mma.sync — tcgen05 rejected by
// this toolchain's sm_103 non-'a' target)
// ---------------------------------------------------------------------------
__device__ __forceinline__ void ldmx4(unsigned* r, unsigned a) {
    asm volatile("ldmatrix.sync.aligned.m8n8.x4.shared.b16 {%0,%1,%2,%3}, [%4];"
        : "=r"(r[0]), "=r"(r[1]), "=r"(r[2]), "=r"(r[3]) : "r"(a));
}
__device__ __forceinline__ void ldmx2(unsigned* r, unsigned a) {
    asm volatile("ldmatrix.sync.aligned.m8n8.x2.shared.b16 {%0,%1}, [%2];"
        : "=r"(r[0]), "=r"(r[1]) : "r"(a));
}
__device__ __forceinline__ void ldmx2t(unsigned* r, unsigned a) {
    asm volatile("ldmatrix.sync.aligned.m8n8.x2.trans.shared.b16 {%0,%1}, [%2];"
        : "=r"(r[0]), "=r"(r[1]) : "r"(a));
}
__device__ __forceinline__ void mma_f16(float* c, const unsigned* a, const unsigned* b) {
    asm volatile("mma.sync.aligned.m16n8k16.row.col.f32.f16.f16.f32 "
        "{%0,%1,%2,%3}, {%4,%5,%6,%7}, {%8,%9}, {%0,%1,%2,%3};"
        : "+f"(c[0]), "+f"(c[1]), "+f"(c[2]), "+f"(c[3])
        : "r"(a[0]), "r"(a[1]), "r"(a[2]), "r"(a[3]), "r"(b[0]), "r"(b[1]));
}
__device__ __forceinline__ void cpa16(unsigned saddr, const void* g) {
    asm volatile("cp.async.cg.shared.global [%0], [%1], 16;"
        :: "r"(saddr), "l"(g) : "memory");
}
#define CPA_COMMIT() asm volatile("cp.async.commit_group;" ::: "memory")
#define CPA_WAIT1()  asm volatile("cp.async.wait_group 1;" ::: "memory")
#define CPA_WAIT0()  asm volatile("cp.async.wait_group 0;" ::: "memory")

__device__ __forceinline__ unsigned packh2(float a, float b) {
    __half2 h = __floats2half2_rn(a, b);
    return *(unsigned*)&h;
}
__device__ __forceinline__ float warpSum(float v) {
    #pragma unroll
    for (int o = 16; o > 0; o >>= 1) v += __shfl_xor_sync(0xffffffffu, v, o);
    return v;
}

// ---------------------------------------------------------------------------
// Warp-level routing
// ---------------------------------------------------------------------------
__device__ __forceinline__ void routing16(const float* u0, const float* u1, float* vout) {
    float b0 = 0.f, b1 = 0.f;
    #pragma unroll
    for (int it = 0; it < 3; it++) {
        float mx = fmaxf(b0, b1);
        float e0 = __expf(b0 - mx), e1 = __expf(b1 - mx);
        float inv = 1.f / (e0 + e1);
        float c0 = e0 * inv, c1 = e1 * inv;
        float loc = 0.f;
        #pragma unroll
        for (int i = 0; i < 16; i++) {
            float s = c0 * u0[i] + c1 * u1[i];
            vout[i] = s;
            loc = fmaf(s, s, loc);
        }
        float n2 = warpSum(loc);
        float nrm = sqrtf(n2);
        float scl = n2 / ((1.f + n2) * (nrm + 1e-9f));
        #pragma unroll
        for (int i = 0; i < 16; i++) vout[i] *= scl;
        if (it < 2) {
            float l0 = 0.f, l1 = 0.f;
            #pragma unroll
            for (int i = 0; i < 16; i++) {
                l0 = fmaf(u0[i], vout[i], l0);
                l1 = fmaf(u1[i], vout[i], l1);
            }
            b0 += warpSum(l0);
            b1 += warpSum(l1);
        }
    }
}

// ---------------------------------------------------------------------------
// Kernel 1: convs + routing, warp-per-row, writes fp16 planes
// ---------------------------------------------------------------------------
__global__ void __launch_bounds__(256) prep_kernel(const float* __restrict__ x,
                                                   const float* __restrict__ w3,
                                                   const float* __restrict__ w5) {
    int wid = threadIdx.x >> 5, lane = threadIdx.x & 31;
    int row = blockIdx.x * 8 + wid;
    int n = row >> 11, l = row & 2047;
    const float* xb = x + (size_t)n * LQ * DD;

    float xv[16], t3[16], t5[16];
    #pragma unroll
    for (int i = 0; i < 16; i++) {
        int c = lane + 32 * i;
        float a3 = 0.f, a5 = 0.f, xx = 0.f;
        #pragma unroll
        for (int j = 0; j < 5; j++) {
            int ll = l - 4 + j;
            xx = (ll >= 0) ? __ldg(xb + (size_t)ll * DD + c) : 0.f;
            a5 = fmaf(w5[c * 5 + j], xx, a5);
            if (j >= 2) a3 = fmaf(w3[c * 3 + (j - 2)], xx, a3);
        }
        xv[i] = xx; t3[i] = a3; t5[i] = a5;
    }

    float u0[16], u1[16], v[16];
    #pragma unroll
    for (int i = 0; i < 16; i++) { u0[i] = xv[i] - t3[i]; u1[i] = xv[i] - t5[i]; }
    routing16(u0, u1, v);
    #pragma unroll
    for (int i = 0; i < 16; i++)
        g_Xs[(size_t)row * DD + lane + 32 * i] = __float2half(v[i]);
    routing16(t3, t5, v);
    #pragma unroll
    for (int i = 0; i < 16; i++)
        g_Xt[(size_t)row * DD + lane + 32 * i] = __float2half(v[i]);
}

__global__ void wsplit_kernel(const float* __restrict__ W) {
    int i = blockIdx.x * 256 + threadIdx.x;
    g_W[i] = __float2half(W[i]);
}

// ---------------------------------------------------------------------------
// attention: windowed flash, fp16, fixed-shift softmax, cp.async K prefetch,
// 4-way split QK accumulator chains. grid=(64, 8, 2), 256 threads, 2 CTAs/SM
// ---------------------------------------------------------------------------
__device__ __forceinline__ void attn_fillK(unsigned sdst, const __half* X, int kb, int tid) {
    #pragma unroll
    for (int i0 = 0; i0 < 8; i0++) {
        int i = tid + i0 * 256;
        int r = i >> 6, c8 = (i & 63) << 3;
        cpa16(sdst + (unsigned)(r * KQS * 2 + c8 * 2), &X[(size_t)(kb * 32 + r) * DD + c8]);
    }
    CPA_COMMIT();
}

__global__ void __launch_bounds__(256, 2) attn_kernel() {
    extern __shared__ char smraw[];
    __half* Qs = (__half*)(smraw + OFF_Q);
    __half* Ps = (__half*)(smraw + OFF_P);
    float* redl = (float*)(smraw + OFF_RED);

    int zb = blockIdx.z;
    const __half* X = (zb ? g_Xt : g_Xs) + (size_t)blockIdx.y * LQ * DD;
    int n = blockIdx.y;
    int qb = blockIdx.x;
    int tid = threadIdx.x;
    int w = tid >> 5, lane = tid & 31;
    int g4 = lane >> 2, tig = lane & 3, lane7 = lane & 7;
    int q0 = qb * 32;
    int rg = w & 1, cg = w >> 1;

    unsigned sb = (unsigned)__cvta_generic_to_shared(smraw);
    int lrow = lane7 + ((lane >> 3) & 1) * 8;
    int lk8b = (lane >> 4) * 16;
    int bk8b = ((lane >> 3) & 1) * 16;

    unsigned aQ   = sb + OFF_Q + (unsigned)((rg * 16 + lrow) * KQS * 2) + lk8b;
    unsigned koff = (unsigned)((cg * 8 + lane7) * KQS * 2) + bk8b;     // + buffer base
    unsigned aP   = sb + OFF_P + (unsigned)((rg * 16 + lrow) * PS2 * 2) + lk8b;
    unsigned voff = (unsigned)(lrow * KQS * 2) + (unsigned)(cg * 256); // + buffer base

    // load Q tile (32 x 512 fp16)
    #pragma unroll
    for (int i0 = 0; i0 < 8; i0++) {
        int i = tid + i0 * 256;
        int r = i >> 6, c8 = (i & 63) << 3;
        *(uint4*)&Qs[r * KQS + c8] = *(const uint4*)&X[(size_t)(q0 + r) * DD + c8];
    }

    float acc[16][4];
    #pragma unroll
    for (int i = 0; i < 16; i++) { acc[i][0] = acc[i][1] = acc[i][2] = acc[i][3] = 0.f; }
    float lsum0 = 0.f, lsum1 = 0.f;

    int par0 = (rg * 16 + g4) * PS2;
    int par1 = (rg * 16 + g4 + 8) * PS2;
    int pc = cg * 8 + 2 * tig;

    int kb0 = (qb >= WTILES) ? qb - WTILES : 0;
    attn_fillK(sb + OFF_K0, X, kb0, tid);     // prologue prefetch

    for (int kb = kb0; kb <= qb; kb++) {
        int cur = (kb - kb0) & 1;
        unsigned kbase = sb + (cur ? OFF_K1 : OFF_K0);
        __syncthreads();                      // prev iter's reads of the other buffer done
        if (kb < qb) {
            attn_fillK(sb + (cur ? OFF_K0 : OFF_K1), X, kb + 1, tid);
            CPA_WAIT1();                      // current buffer's group complete
        } else {
            CPA_WAIT0();
        }
        __syncthreads();                      // K tile visible to all warps

        // scores: S = Q K^T, 4 independent accumulator chains
        float s4[4][4];
        #pragma unroll
        for (int i = 0; i < 4; i++) { s4[i][0] = s4[i][1] = s4[i][2] = s4[i][3] = 0.f; }
        unsigned bK = kbase + koff;
        #pragma unroll 8
        for (int ks2 = 0; ks2 < 32; ks2++) {
            unsigned o = ks2 * 32;
            unsigned ah[4], bh[2];
            ldmx4(ah, aQ + o);
            ldmx2(bh, bK + o);
            mma_f16(s4[ks2 & 3], ah, bh);
        }
        float sc[4];
        #pragma unroll
        for (int i = 0; i < 4; i++)
            sc[i] = (s4[0][i] + s4[1][i]) + (s4[2][i] + s4[3][i]);

        int r0 = q0 + rg * 16 + g4, r1 = r0 + 8;
        int c0 = kb * 32 + cg * 8 + 2 * tig, c1 = c0 + 1;
        float p0 = (r0 >= c0) ? __expf(sc[0] - DECAYF * (float)(r0 - c0)) : 0.f;
        float p1 = (r0 >= c1) ? __expf(sc[1] - DECAYF * (float)(r0 - c1)) : 0.f;
        float p2 = (r1 >= c0) ? __expf(sc[2] - DECAYF * (float)(r1 - c0)) : 0.f;
        float p3 = (r1 >= c1) ? __expf(sc[3] - DECAYF * (float)(r1 - c1)) : 0.f;
        lsum0 += p0 + p1;
        lsum1 += p2 + p3;
        *(unsigned*)&Ps[par0 + pc] = packh2(p0, p1);
        *(unsigned*)&Ps[par1 + pc] = packh2(p2, p3);
        __syncthreads();                      // P tile ready

        // PV: O += P V (16 independent chains)
        unsigned bV = kbase + voff;
        #pragma unroll
        for (int ks2 = 0; ks2 < 2; ks2++) {
            unsigned ah[4];
            ldmx4(ah, aP + ks2 * 32);
            unsigned vh = bV + (unsigned)(ks2 * 16 * KQS * 2);
            #pragma unroll
            for (int nf = 0; nf < 16; nf++) {
                unsigned bh[2];
                ldmx2t(bh, vh + nf * 16);
                mma_f16(acc[nf], ah, bh);
            }
        }
    }

    lsum0 += __shfl_xor_sync(0xffffffffu, lsum0, 1);
    lsum0 += __shfl_xor_sync(0xffffffffu, lsum0, 2);
    lsum1 += __shfl_xor_sync(0xffffffffu, lsum1, 1);
    lsum1 += __shfl_xor_sync(0xffffffffu, lsum1, 2);
    __syncthreads();
    if (tig == 0) {
        redl[cg * 32 + rg * 16 + g4]     = lsum0;
        redl[cg * 32 + rg * 16 + g4 + 8] = lsum1;
    }
    __syncthreads();
    int row0 = rg * 16 + g4;
    float lt0 = redl[row0] + redl[32 + row0] + redl[64 + row0] + redl[96 + row0];
    float lt1 = redl[row0 + 8] + redl[32 + row0 + 8] + redl[64 + row0 + 8] + redl[96 + row0 + 8];
    float li0 = 1.f / lt0;
    float li1 = 1.f / lt1;

    size_t orow0 = (size_t)(n * LQ + q0 + row0) * (2 * DD);
    size_t orow1 = orow0 + (size_t)8 * (2 * DD);
    #pragma unroll
    for (int nf = 0; nf < 16; nf++) {
        int col = zb * DD + cg * 128 + nf * 8 + 2 * tig;
        *(unsigned*)&g_cat[orow0 + col] = packh2(acc[nf][0] * li0, acc[nf][1] * li0);
        *(unsigned*)&g_cat[orow1 + col] = packh2(acc[nf][2] * li1, acc[nf][3] * li1);
    }
}

// ---------------------------------------------------------------------------
// fusion: out[16384,512] = cat @ W^T + bias, fp16
// CTA 128x64, warp 32x32, K-chunk 64, double-buffered cp.async, 4 CTAs/SM
// ---------------------------------------------------------------------------
__device__ __forceinline__ void fus_fill(unsigned sbuf, int kc, int bm, int bn, int tid) {
    // A: 128 rows x 64 k (4 x 16B per thread)
    #pragma unroll
    for (int i = 0; i < 4; i++) {
        int idx = tid + i * 256;
        int r = idx >> 3, c8 = (idx & 7) << 3;
        cpa16(sbuf + F_A + (unsigned)(r * FROWB + c8 * 2),
              &g_cat[(size_t)(bm + r) * 1024 + kc * 64 + c8]);
    }
    // B: 64 rows x 64 k (2 x 16B per thread)
    #pragma unroll
    for (int i = 0; i < 2; i++) {
        int idx = tid + i * 256;
        int r = idx >> 3, c8 = (idx & 7) << 3;
        cpa16(sbuf + F_B + (unsigned)(r * FROWB + c8 * 2),
              &g_W[(size_t)(bn + r) * 1024 + kc * 64 + c8]);
    }
    CPA_COMMIT();
}

__global__ void __launch_bounds__(256, 4) fusion_kernel(const float* __restrict__ bias,
                                                        float* __restrict__ out) {
    extern __shared__ char fsm[];
    unsigned sb = (unsigned)__cvta_generic_to_shared(fsm);
    int tid = threadIdx.x;
    int w = tid >> 5, lane = tid & 31;
    int g4 = lane >> 2, tig = lane & 3, lane7 = lane & 7;
    int rg = w & 3, cg = w >> 2;
    int bm = blockIdx.x * 128;
    int bn = blockIdx.y * 64;
    int lrow = lane7 + ((lane >> 3) & 1) * 8;
    int lk8b = (lane >> 4) * 16;
    int bk8b = ((lane >> 3) & 1) * 16;

    float acc[2][4][4];
    #pragma unroll
    for (int t = 0; t < 2; t++)
        #pragma unroll
        for (int nf = 0; nf < 4; nf++) {
            acc[t][nf][0] = 0.f; acc[t][nf][1] = 0.f;
            acc[t][nf][2] = 0.f; acc[t][nf][3] = 0.f;
        }

    fus_fill(sb, 0, bm, bn, tid);
    fus_fill(sb + F_BUF, 1, bm, bn, tid);

    unsigned aoff0 = (unsigned)((rg * 32 + lrow) * FROWB) + lk8b;
    unsigned aoff1 = (unsigned)((rg * 32 + 16 + lrow) * FROWB) + lk8b;
    unsigned boffs[4];
    #pragma unroll
    for (int nf = 0; nf < 4; nf++)
        boffs[nf] = (unsigned)((cg * 32 + nf * 8 + lane7) * FROWB) + bk8b;

    for (int c = 0; c < FNCH; c++) {
        unsigned base = sb + (unsigned)(c & 1) * F_BUF;
        if (c == FNCH - 1) { CPA_WAIT0(); } else { CPA_WAIT1(); }
        __syncthreads();

        #pragma unroll
        for (int ks = 0; ks < 4; ks++) {
            unsigned ko = (unsigned)(ks * 32);
            unsigned ah0[4], ah1[4];
            ldmx4(ah0, base + F_A + aoff0 + ko);
            ldmx4(ah1, base + F_A + aoff1 + ko);
            unsigned bh[4][2];
            #pragma unroll
            for (int nf = 0; nf < 4; nf++)
                ldmx2(bh[nf], base + F_B + boffs[nf] + ko);
            #pragma unroll
            for (int nf = 0; nf < 4; nf++) {
                mma_f16(acc[0][nf], ah0, bh[nf]);
                mma_f16(acc[1][nf], ah1, bh[nf]);
            }
        }
        __syncthreads();
        if (c + 2 < FNCH) fus_fill(base, c + 2, bm, bn, tid);
    }

    #pragma unroll
    for (int t = 0; t < 2; t++) {
        int orow0 = bm + rg * 32 + t * 16 + g4;
        int orow1 = orow0 + 8;
        #pragma unroll
        for (int nf = 0; nf < 4; nf++) {
            int col = bn + cg * 32 + nf * 8 + 2 * tig;
            float b0v = bias[col], b1v = bias[col + 1];
            *(float2*)&out[(size_t)orow0 * 512 + col] =
                make_float2(acc[t][nf][0] + b0v, acc[t][nf][1] + b1v);
            *(float2*)&out[(size_t)orow1 * 512 + col] =
                make_float2(acc[t][nf][2] + b0v, acc[t][nf][3] + b1v);
        }
    }
}

// ---------------------------------------------------------------------------
extern "C" void kernel_launch(void* const* d_in, const int* in_sizes, int n_in,
                              void* d_out, int out_size) {
    const float* x  = (const float*)d_in[0];
    const float* w3 = (const float*)d_in[1];
    const float* w5 = (const float*)d_in[2];
    const float* fw = (const float*)d_in[3];
    const float* fb = (const float*)d_in[4];
    float* out = (float*)d_out;

    prep_kernel<<<NB * LQ / 8, 256>>>(x, w3, w5);
    wsplit_kernel<<<(DD * 2 * DD) / 256, 256>>>(fw);

    cudaFuncSetAttribute(attn_kernel,
                         cudaFuncAttributeMaxDynamicSharedMemorySize, SMEM_ATTN);
    dim3 ga(LQ / 32, NB, 2);
    attn_kernel<<<ga, 256, SMEM_ATTN>>>();

    cudaFuncSetAttribute(fusion_kernel,
                         cudaFuncAttributeMaxDynamicSharedMemorySize, SMEM_FUS);
    dim3 gf((NB * LQ) / 128, DD / 64);
    fusion_kernel<<<gf, 256, SMEM_FUS>>>(fb, out);
}